// round 10
// baseline (speedup 1.0000x reference)
#include <cuda_runtime.h>
#include <cuda_fp16.h>
#include <cstdint>
#include <math.h>

// -------- problem shape --------
#define BHN    64
#define MSEQ   1024
#define DIMN   64
#define LSPAN  1024
#define KVROWS (MSEQ + LSPAN)
#define BM     32
#define BL     128
#define RW     160          // BM + BL
#define NT     (LSPAN / BL)
#define NTHR   256

// -------- fp16 preconverted operands (device scratch; allocation-free) --------
__device__ __half g_Qh [(size_t)BHN * MSEQ  * DIMN];   //  8 MB, [bh][i][d]
__device__ __half g_Kh [(size_t)BHN * KVROWS * DIMN];  // 16 MB, [bh][j][d]
__device__ __half g_VTh[(size_t)BHN * DIMN * KVROWS];  // 16 MB, [bh][d][j]
__device__ __half g_PTh[(size_t)LSPAN * DIMN];         // 128 KB, [l][d]

// -------- smem byte offsets --------
#define QS_B 0        // Q    [32][72]  f16 =  4608
#define KS_B 4608     // K    [160][72] f16 = 23040
#define VT_B 27648    // V^T  [64][168] f16 = 21504
#define PT_B 49152    // P^T  [128][72] f16 = 18432
#define WS_B 67584    // W    [32][168] f16 = 10752
#define PS_B 78336    // posS [32][132] f32 = 16896
#define RS_B 95232    // rowsums [32]   f32 =   128
#define OB_B KS_B     // O-reduce [32][68] f32 (post-loop, reuses K)
#define SMEM_BYTES 95360

// -------- b32 strides --------
#define QS2 36
#define KS2 36
#define PT2 36
#define VT2 84
#define WS2 84
#define PSF 132
#define OBF 68

__device__ __forceinline__ uint32_t smem_u32(const void* p) {
    uint32_t a;
    asm("{ .reg .u64 t; cvta.to.shared.u64 t, %1; cvt.u32.u64 %0, t; }" : "=r"(a) : "l"(p));
    return a;
}
__device__ __forceinline__ void cp16(uint32_t dst, const void* src) {
    asm volatile("cp.async.ca.shared.global [%0], [%1], 16;" :: "r"(dst), "l"(src) : "memory");
}
#define CP_COMMIT() asm volatile("cp.async.commit_group;" ::: "memory")
#define CP_WAIT0()  asm volatile("cp.async.wait_group 0;" ::: "memory")
#define CP_WAIT1()  asm volatile("cp.async.wait_group 1;" ::: "memory")

__device__ __forceinline__ void mma_f16(float c[4], const uint32_t a[4], const uint32_t b[2]) {
    asm volatile(
        "mma.sync.aligned.m16n8k16.row.col.f32.f16.f16.f32 "
        "{%0,%1,%2,%3}, {%4,%5,%6,%7}, {%8,%9}, {%0,%1,%2,%3};"
        : "+f"(c[0]), "+f"(c[1]), "+f"(c[2]), "+f"(c[3])
        : "r"(a[0]), "r"(a[1]), "r"(a[2]), "r"(a[3]), "r"(b[0]), "r"(b[1]));
}

// ================= pre-pass: f32 -> f16 (rna), V/P transposed =================
__global__ void prep_qkv(const float* __restrict__ Q, const float* __restrict__ K,
                         const float* __restrict__ V) {
    const int x = blockIdx.x, bh = blockIdx.y, tid = threadIdx.x;
    if (x < 16) {
        size_t base = ((size_t)bh * MSEQ + x * 64) * DIMN;
        #pragma unroll
        for (int p = 0; p < 4; p++) {
            int idx = p * 256 + tid;
            float4 v = *(const float4*)(Q + base + (size_t)idx * 4);
            __half2 h0 = __floats2half2_rn(v.x, v.y);
            __half2 h1 = __floats2half2_rn(v.z, v.w);
            *(uint2*)(&g_Qh[base + (size_t)idx * 4]) =
                make_uint2(*(uint32_t*)&h0, *(uint32_t*)&h1);
        }
    } else if (x < 48) {
        size_t base = ((size_t)bh * KVROWS + (x - 16) * 64) * DIMN;
        #pragma unroll
        for (int p = 0; p < 4; p++) {
            int idx = p * 256 + tid;
            float4 v = *(const float4*)(K + base + (size_t)idx * 4);
            __half2 h0 = __floats2half2_rn(v.x, v.y);
            __half2 h1 = __floats2half2_rn(v.z, v.w);
            *(uint2*)(&g_Kh[base + (size_t)idx * 4]) =
                make_uint2(*(uint32_t*)&h0, *(uint32_t*)&h1);
        }
    } else {
        __shared__ float ts[64][65];   // [j][d]
        const int j0 = (x - 48) * 64;
        size_t base = ((size_t)bh * KVROWS + j0) * DIMN;
        #pragma unroll
        for (int p = 0; p < 16; p++) {
            int idx = p * 256 + tid;
            ts[idx >> 6][idx & 63] = V[base + idx];
        }
        __syncthreads();
        const int d = tid >> 2, jq = (tid & 3) * 16;
        uint32_t u[8];
        #pragma unroll
        for (int q = 0; q < 8; q++) {
            __half2 h = __floats2half2_rn(ts[jq + 2 * q][d], ts[jq + 2 * q + 1][d]);
            u[q] = *(uint32_t*)&h;
        }
        __half* dst = &g_VTh[((size_t)bh * DIMN + d) * KVROWS + j0 + jq];
        *(uint4*)dst       = make_uint4(u[0], u[1], u[2], u[3]);
        *(uint4*)(dst + 8) = make_uint4(u[4], u[5], u[6], u[7]);
    }
}

__global__ void prep_pt(const float* __restrict__ P) {
    __shared__ float ts[64][65];   // [l][d]
    const int l0 = blockIdx.x * 64, tid = threadIdx.x;
    #pragma unroll
    for (int p = 0; p < 16; p++) {
        int idx = p * 256 + tid;
        int d = idx >> 6, lq = idx & 63;
        ts[lq][d] = P[(size_t)d * LSPAN + l0 + lq];
    }
    __syncthreads();
    const int lq = tid >> 2, dq = (tid & 3) * 16;
    uint32_t u[8];
    #pragma unroll
    for (int q = 0; q < 8; q++) {
        __half2 h = __floats2half2_rn(ts[lq][dq + 2 * q], ts[lq][dq + 2 * q + 1]);
        u[q] = *(uint32_t*)&h;
    }
    __half* dst = &g_PTh[(size_t)(l0 + lq) * DIMN + dq];
    *(uint4*)dst       = make_uint4(u[0], u[1], u[2], u[3]);
    *(uint4*)(dst + 8) = make_uint4(u[4], u[5], u[6], u[7]);
}

// ================= main kernel: BM=32, 256 thr, 2 CTAs/SM =================
__global__ void __launch_bounds__(NTHR, 2) seqattn_f16_kernel(float* __restrict__ O) {
    extern __shared__ char sm[];
    const uint32_t sb = smem_u32(sm);

    const uint32_t* Qsu = (const uint32_t*)(sm + QS_B);
    const uint32_t* Ksu = (const uint32_t*)(sm + KS_B);
    const uint32_t* Vtu = (const uint32_t*)(sm + VT_B);
    const uint32_t* Ptu = (const uint32_t*)(sm + PT_B);
    uint32_t*       Wsu = (uint32_t*)(sm + WS_B);
    float*          psf = (float*)(sm + PS_B);
    float*          Rs  = (float*)(sm + RS_B);

    const int tid  = threadIdx.x;
    const int w    = tid >> 5;
    const int lane = tid & 31;
    const int g    = lane >> 2;
    const int tig  = lane & 3;

    // S GEMM / exp layout: 2m x 4n warps (16 rows, 40 content + 32 pos cols each)
    const int wm = w >> 2;
    const int wn = w & 3;
    // PV layout: 2 k-groups x (2m x 2n)
    const int kg  = w & 1;           // 80 k each
    const int ww  = w >> 1;          // 0..3
    const int wmP = ww >> 1;         // 16 rows
    const int wnP = ww & 1;          // 32 cols

    const int bh = blockIdx.y;
    const int m0 = blockIdx.x * BM;

    const __half* Qh  = g_Qh  + ((size_t)bh * MSEQ + m0) * DIMN;
    const __half* Kh  = g_Kh  + (size_t)bh * KVROWS * DIMN;
    const __half* VTh = g_VTh + (size_t)bh * DIMN * KVROWS;

    // ---- preamble: prefetch Q, K(0), PT(0) (group A) then V(0) (group B) ----
    {
        int r = tid >> 3, c = tid & 7;
        cp16(sb + QS_B + (uint32_t)(r * 72 + c * 8) * 2u, Qh + (size_t)r * DIMN + c * 8);
        #pragma unroll
        for (int p = 0; p < 5; p++) {   // K(0): 160 rows x 8 chunks
            int idx = p * NTHR + tid;
            int kr = idx >> 3, kc = idx & 7;
            cp16(sb + KS_B + (uint32_t)(kr * 72 + kc * 8) * 2u,
                 Kh + (size_t)(m0 + kr) * DIMN + kc * 8);
        }
        #pragma unroll
        for (int p = 0; p < 4; p++) {   // PT(0): 128 rows x 8 chunks
            int idx = p * NTHR + tid;
            int pr = idx >> 3, pc = idx & 7;
            cp16(sb + PT_B + (uint32_t)(pr * 72 + pc * 8) * 2u,
                 g_PTh + (size_t)pr * DIMN + pc * 8);
        }
        CP_COMMIT();
        #pragma unroll
        for (int p = 0; p < 5; p++) {   // V(0): 64 d-rows x 20 chunks
            int idx = p * NTHR + tid;
            int d = idx / 20, c20 = idx % 20;
            cp16(sb + VT_B + (uint32_t)(d * 168 + c20 * 8) * 2u,
                 VTh + (size_t)d * KVROWS + m0 + c20 * 8);
        }
        CP_COMMIT();
    }
    if (tid < 32) Rs[tid] = 0.f;

    float cO[4][4];
    #pragma unroll
    for (int b = 0; b < 4; b++)
        #pragma unroll
        for (int c = 0; c < 4; c++) cO[b][c] = 0.f;
    float rsv[2] = {0.f, 0.f};

    for (int lt = 0; lt < NT; lt++) {
        CP_WAIT1();        // Q/K/PT of this tile arrived (V may be in flight)
        __syncthreads();

        // ========== S GEMM: content 32x160 + pos 32x128 (fp16, k=64) ==========
        float cC[5][4], cP[4][4];
        #pragma unroll
        for (int nb = 0; nb < 5; nb++)
            #pragma unroll
            for (int c = 0; c < 4; c++) cC[nb][c] = 0.f;
        #pragma unroll
        for (int nb = 0; nb < 4; nb++)
            #pragma unroll
            for (int c = 0; c < 4; c++) cP[nb][c] = 0.f;

        #pragma unroll
        for (int ks = 0; ks < 4; ks++) {
            const int c2 = ks * 8 + tig;
            const int row = wm * 16 + g;
            uint32_t a[4];
            a[0] = Qsu[row * QS2 + c2];
            a[1] = Qsu[(row + 8) * QS2 + c2];
            a[2] = Qsu[row * QS2 + c2 + 4];
            a[3] = Qsu[(row + 8) * QS2 + c2 + 4];
            #pragma unroll
            for (int nb = 0; nb < 4; nb++) {       // pos
                int n = wn * 32 + nb * 8 + g;
                uint32_t b[2] = { Ptu[n * PT2 + c2], Ptu[n * PT2 + c2 + 4] };
                mma_f16(cP[nb], a, b);
            }
            #pragma unroll
            for (int nb = 0; nb < 5; nb++) {       // content
                int n = wn * 40 + nb * 8 + g;
                uint32_t b[2] = { Ksu[n * KS2 + c2], Ksu[n * KS2 + c2 + 4] };
                mma_f16(cC[nb], a, b);
            }
        }

        // ---- pos scores -> posS ----
        #pragma unroll
        for (int nb = 0; nb < 4; nb++) {
            int lp = wn * 32 + nb * 8 + 2 * tig;
            int i1 = wm * 16 + g;
            *(float2*)(psf + i1 * PSF + lp)       = make_float2(cP[nb][0], cP[nb][1]);
            *(float2*)(psf + (i1 + 8) * PSF + lp) = make_float2(cP[nb][2], cP[nb][3]);
        }
        __syncthreads();   // sync1: posS visible; Ks/Pts/Qs reads done

        // prefetch next K + PT (one group)
        if (lt < NT - 1) {
            const int jg0n = m0 + (lt + 1) * BL;
            #pragma unroll
            for (int p = 0; p < 5; p++) {
                int idx = p * NTHR + tid;
                int kr = idx >> 3, kc = idx & 7;
                cp16(sb + KS_B + (uint32_t)(kr * 72 + kc * 8) * 2u,
                     Kh + (size_t)(jg0n + kr) * DIMN + kc * 8);
            }
            #pragma unroll
            for (int p = 0; p < 4; p++) {
                int idx = p * NTHR + tid;
                int pr = idx >> 3, pc = idx & 7;
                cp16(sb + PT_B + (uint32_t)(pr * 72 + pc * 8) * 2u,
                     g_PTh + (size_t)((lt + 1) * BL + pr) * DIMN + pc * 8);
            }
            CP_COMMIT();
        }

        // ---- exp + banded W (f16x2) + rowsums ----
        #pragma unroll
        for (int nb = 0; nb < 5; nb++) {
            int j0 = wn * 40 + nb * 8 + 2 * tig;
            #pragma unroll
            for (int h = 0; h < 2; h++) {
                int i = wm * 16 + g + 8 * h;
                float s0 = cC[nb][2 * h], s1 = cC[nb][2 * h + 1];
                int l0 = j0 - i;
                float w0 = 0.f, w1 = 0.f;
                if (l0 >= 0 && l0 < 128)
                    w0 = __expf((s0 + psf[i * PSF + l0]) * 0.125f);
                if (l0 + 1 >= 0 && l0 + 1 < 128)
                    w1 = __expf((s1 + psf[i * PSF + l0 + 1]) * 0.125f);
                __half2 hw = __floats2half2_rn(w0, w1);
                float2 bk = __half22float2(hw);
                rsv[h] += bk.x + bk.y;
                Wsu[i * WS2 + (j0 >> 1)] = *(uint32_t*)&hw;
            }
        }

        // V(t) must be resident before PV
        if (lt < NT - 1) { CP_WAIT1(); } else { CP_WAIT0(); }
        __syncthreads();   // sync2: Ws visible, V visible

        // ========== PV: cO += W[32x160] * V[160x64] (k-split x2) ==========
        #pragma unroll
        for (int kk = 0; kk < 5; kk++) {
            const int kb2 = kg * 40 + kk * 8 + tig;
            const int row = wmP * 16 + g;
            uint32_t a[4];
            a[0] = Wsu[row * WS2 + kb2];
            a[1] = Wsu[(row + 8) * WS2 + kb2];
            a[2] = Wsu[row * WS2 + kb2 + 4];
            a[3] = Wsu[(row + 8) * WS2 + kb2 + 4];
            #pragma unroll
            for (int nb = 0; nb < 4; nb++) {
                int d = wnP * 32 + nb * 8 + g;
                uint32_t b[2] = { Vtu[d * VT2 + kb2], Vtu[d * VT2 + kb2 + 4] };
                mma_f16(cO[nb], a, b);
            }
        }
        __syncthreads();   // sync3: Vts/Ws reads done

        // prefetch next V
        if (lt < NT - 1) {
            const int jg0n = m0 + (lt + 1) * BL;
            #pragma unroll
            for (int p = 0; p < 5; p++) {
                int idx = p * NTHR + tid;
                int d = idx / 20, c20 = idx % 20;
                cp16(sb + VT_B + (uint32_t)(d * 168 + c20 * 8) * 2u,
                     VTh + (size_t)d * KVROWS + jg0n + c20 * 8);
            }
            CP_COMMIT();
        }
    }

    // ---- rowsum reduction ----
    #pragma unroll
    for (int h = 0; h < 2; h++) {
        float v = rsv[h];
        v += __shfl_xor_sync(0xffffffffu, v, 1);
        v += __shfl_xor_sync(0xffffffffu, v, 2);
        if (tig == 0) {
            int i = wm * 16 + g + 8 * h;
            atomicAdd(&Rs[i], v);
        }
    }
    __syncthreads();   // all PV done; K buffer reusable as Ob

    // ---- k-group reduction of cO into Ob ----
    float* Ob = (float*)(sm + OB_B);
    #pragma unroll
    for (int step = 0; step < 2; step++) {
        if (kg == step) {
            #pragma unroll
            for (int nb = 0; nb < 4; nb++) {
                int row = wmP * 16 + g;
                int col = wnP * 32 + nb * 8 + 2 * tig;
                if (step == 0) {
                    *(float2*)(Ob + row * OBF + col)       = make_float2(cO[nb][0], cO[nb][1]);
                    *(float2*)(Ob + (row + 8) * OBF + col) = make_float2(cO[nb][2], cO[nb][3]);
                } else {
                    float2 p0 = *(float2*)(Ob + row * OBF + col);
                    float2 p1 = *(float2*)(Ob + (row + 8) * OBF + col);
                    p0.x += cO[nb][0]; p0.y += cO[nb][1];
                    p1.x += cO[nb][2]; p1.y += cO[nb][3];
                    *(float2*)(Ob + row * OBF + col)       = p0;
                    *(float2*)(Ob + (row + 8) * OBF + col) = p1;
                }
            }
        }
        __syncthreads();
    }

    // ---- normalize + store ----
    {
        int row = tid >> 3;
        int c8  = (tid & 7) * 8;
        float inv = 1.f / Rs[row];
        float4 o0 = *(float4*)(Ob + row * OBF + c8);
        float4 o1 = *(float4*)(Ob + row * OBF + c8 + 4);
        o0.x *= inv; o0.y *= inv; o0.z *= inv; o0.w *= inv;
        o1.x *= inv; o1.y *= inv; o1.z *= inv; o1.w *= inv;
        float* orow = O + ((size_t)bh * MSEQ + m0 + row) * DIMN + c8;
        *(float4*)(orow)     = o0;
        *(float4*)(orow + 4) = o1;
    }
}

extern "C" void kernel_launch(void* const* d_in, const int* in_sizes, int n_in,
                              void* d_out, int out_size) {
    const float* Q = (const float*)d_in[0];
    const float* K = (const float*)d_in[1];
    const float* V = (const float*)d_in[2];
    const float* P = (const float*)d_in[3];
    float* O = (float*)d_out;
    (void)n_in; (void)in_sizes; (void)out_size;

    // pre-pass: f32 -> f16 (rna), V and P transposed
    prep_qkv<<<dim3(80, BHN), 256>>>(Q, K, V);
    prep_pt<<<16, 256>>>(P);

    cudaFuncSetAttribute(seqattn_f16_kernel,
                         cudaFuncAttributeMaxDynamicSharedMemorySize, SMEM_BYTES);
    dim3 grid(MSEQ / BM, BHN);   // (32, 64)
    seqattn_f16_kernel<<<grid, NTHR, SMEM_BYTES>>>(O);
}

// round 11
// speedup vs baseline: 1.0377x; 1.0377x over previous
#include <cuda_runtime.h>
#include <cuda_fp16.h>
#include <cstdint>
#include <math.h>

// -------- problem shape --------
#define BHN    64
#define MSEQ   1024
#define DIMN   64
#define LSPAN  1024
#define KVROWS (MSEQ + LSPAN)
#define BM     64
#define BL     128
#define NT     (LSPAN / BL)
#define NTHR   512

// -------- fp16 preconverted operands (device scratch; allocation-free) --------
__device__ __half g_Qh [(size_t)BHN * MSEQ  * DIMN];   //  8 MB, [bh][i][d]
__device__ __half g_Kh [(size_t)BHN * KVROWS * DIMN];  // 16 MB, [bh][j][d]
__device__ __half g_VTh[(size_t)BHN * DIMN * KVROWS];  // 16 MB, [bh][d][j]
__device__ __half g_PTh[(size_t)LSPAN * DIMN];         // 128 KB, [l][d]

// -------- smem byte offsets (double-buffered K/VT/PT) --------
#define QS_B 0                      // Q  [64][72h]        =  9216
#define KS_B 9216                   // K  2x [192][72h]    = 55296
#define VT_B 64512                  // V^T 2x [64][200h]   = 51200
#define PT_B 115712                 // P^T 2x [128][72h]   = 36864
#define WS_B 152576                 // W  [64][200h]       = 25600
#define PS_B 178176                 // posS [64][132] f32  = 33792
#define RS_B 211968                 // rowsums [64] f32    =   256
#define SMEM_BYTES 212224

// buffer sizes in b32
#define KSZ 6912
#define VSZ 6400
#define PSZ 4608

// -------- b32 strides --------
#define QS2 36
#define KS2 36
#define PT2 36
#define VT2 100
#define WS2 100
#define PSF 132

__device__ __forceinline__ uint32_t smem_u32(const void* p) {
    uint32_t a;
    asm("{ .reg .u64 t; cvta.to.shared.u64 t, %1; cvt.u32.u64 %0, t; }" : "=r"(a) : "l"(p));
    return a;
}
__device__ __forceinline__ void cp16(uint32_t dst, const void* src) {
    asm volatile("cp.async.ca.shared.global [%0], [%1], 16;" :: "r"(dst), "l"(src) : "memory");
}
#define CP_COMMIT() asm volatile("cp.async.commit_group;" ::: "memory")
#define CP_WAIT1()  asm volatile("cp.async.wait_group 1;" ::: "memory")

__device__ __forceinline__ void mma_f16_f32(float c[4], const uint32_t a[4], const uint32_t b[2]) {
    asm volatile(
        "mma.sync.aligned.m16n8k16.row.col.f32.f16.f16.f32 "
        "{%0,%1,%2,%3}, {%4,%5,%6,%7}, {%8,%9}, {%0,%1,%2,%3};"
        : "+f"(c[0]), "+f"(c[1]), "+f"(c[2]), "+f"(c[3])
        : "r"(a[0]), "r"(a[1]), "r"(a[2]), "r"(a[3]), "r"(b[0]), "r"(b[1]));
}
__device__ __forceinline__ void mma_f16_f16(uint32_t c[2], const uint32_t a[4], const uint32_t b[2]) {
    asm volatile(
        "mma.sync.aligned.m16n8k16.row.col.f16.f16.f16.f16 "
        "{%0,%1}, {%2,%3,%4,%5}, {%6,%7}, {%0,%1};"
        : "+r"(c[0]), "+r"(c[1])
        : "r"(a[0]), "r"(a[1]), "r"(a[2]), "r"(a[3]), "r"(b[0]), "r"(b[1]));
}

// ================= pre-pass: f32 -> f16 (rna), V/P transposed =================
__global__ void prep_qkv(const float* __restrict__ Q, const float* __restrict__ K,
                         const float* __restrict__ V) {
    const int x = blockIdx.x, bh = blockIdx.y, tid = threadIdx.x;
    if (x < 16) {
        size_t base = ((size_t)bh * MSEQ + x * 64) * DIMN;
        #pragma unroll
        for (int p = 0; p < 4; p++) {
            int idx = p * 256 + tid;
            float4 v = *(const float4*)(Q + base + (size_t)idx * 4);
            __half2 h0 = __floats2half2_rn(v.x, v.y);
            __half2 h1 = __floats2half2_rn(v.z, v.w);
            *(uint2*)(&g_Qh[base + (size_t)idx * 4]) =
                make_uint2(*(uint32_t*)&h0, *(uint32_t*)&h1);
        }
    } else if (x < 48) {
        size_t base = ((size_t)bh * KVROWS + (x - 16) * 64) * DIMN;
        #pragma unroll
        for (int p = 0; p < 4; p++) {
            int idx = p * 256 + tid;
            float4 v = *(const float4*)(K + base + (size_t)idx * 4);
            __half2 h0 = __floats2half2_rn(v.x, v.y);
            __half2 h1 = __floats2half2_rn(v.z, v.w);
            *(uint2*)(&g_Kh[base + (size_t)idx * 4]) =
                make_uint2(*(uint32_t*)&h0, *(uint32_t*)&h1);
        }
    } else {
        __shared__ float ts[64][65];   // [j][d]
        const int j0 = (x - 48) * 64;
        size_t base = ((size_t)bh * KVROWS + j0) * DIMN;
        #pragma unroll
        for (int p = 0; p < 16; p++) {
            int idx = p * 256 + tid;
            ts[idx >> 6][idx & 63] = V[base + idx];
        }
        __syncthreads();
        const int d = tid >> 2, jq = (tid & 3) * 16;
        uint32_t u[8];
        #pragma unroll
        for (int q = 0; q < 8; q++) {
            __half2 h = __floats2half2_rn(ts[jq + 2 * q][d], ts[jq + 2 * q + 1][d]);
            u[q] = *(uint32_t*)&h;
        }
        __half* dst = &g_VTh[((size_t)bh * DIMN + d) * KVROWS + j0 + jq];
        *(uint4*)dst       = make_uint4(u[0], u[1], u[2], u[3]);
        *(uint4*)(dst + 8) = make_uint4(u[4], u[5], u[6], u[7]);
    }
}

__global__ void prep_pt(const float* __restrict__ P) {
    __shared__ float ts[64][65];   // [l][d]
    const int l0 = blockIdx.x * 64, tid = threadIdx.x;
    #pragma unroll
    for (int p = 0; p < 16; p++) {
        int idx = p * 256 + tid;
        int d = idx >> 6, lq = idx & 63;
        ts[lq][d] = P[(size_t)d * LSPAN + l0 + lq];
    }
    __syncthreads();
    const int lq = tid >> 2, dq = (tid & 3) * 16;
    uint32_t u[8];
    #pragma unroll
    for (int q = 0; q < 8; q++) {
        __half2 h = __floats2half2_rn(ts[lq][dq + 2 * q], ts[lq][dq + 2 * q + 1]);
        u[q] = *(uint32_t*)&h;
    }
    __half* dst = &g_PTh[(size_t)(l0 + lq) * DIMN + dq];
    *(uint4*)dst       = make_uint4(u[0], u[1], u[2], u[3]);
    *(uint4*)(dst + 8) = make_uint4(u[4], u[5], u[6], u[7]);
}

// ================= main kernel: m16 band windows, 512 thr =================
__global__ void __launch_bounds__(NTHR, 1) seqattn_f16_kernel(float* __restrict__ O) {
    extern __shared__ char sm[];
    const uint32_t sb = smem_u32(sm);

    const uint32_t* Qsu = (const uint32_t*)(sm + QS_B);
    uint32_t*       Wsu = (uint32_t*)(sm + WS_B);
    float*          psf = (float*)(sm + PS_B);
    float*          Rs  = (float*)(sm + RS_B);

    const int tid  = threadIdx.x;
    const int w    = tid >> 5;
    const int lane = tid & 31;
    const int g    = lane >> 2;
    const int tig  = lane & 3;

    // 16 warps = 4 m-groups (16 rows each, window base wm*16) x 4 n-warps
    const int wm = w >> 2;
    const int wn = w & 3;
    // content window: 18 blocks of 8 cols; wn gets {5,5,4,4} blocks
    const int nstart = (wn < 2) ? wn * 5 : 10 + (wn - 2) * 4;
    const int ncnt   = (wn < 2) ? 5 : 4;

    const int bh = blockIdx.y;
    const int m0 = blockIdx.x * BM;

    const __half* Qh  = g_Qh  + ((size_t)bh * MSEQ + m0) * DIMN;
    const __half* Kh  = g_Kh  + (size_t)bh * KVROWS * DIMN;
    const __half* VTh = g_VTh + (size_t)bh * DIMN * KVROWS;

    // ---- preamble: Q + K(0) + PT(0) (group0), V(0) (group1) ----
    {
        int r = tid >> 3, c = tid & 7;
        cp16(sb + QS_B + (uint32_t)(r * 72 + c * 8) * 2u, Qh + (size_t)r * DIMN + c * 8);
        #pragma unroll
        for (int p = 0; p < 3; p++) {   // K(0): 192 rows x 8 chunks
            int idx = p * NTHR + tid;
            int kr = idx >> 3, kc = idx & 7;
            cp16(sb + KS_B + (uint32_t)(kr * 72 + kc * 8) * 2u,
                 Kh + (size_t)(m0 + kr) * DIMN + kc * 8);
        }
        #pragma unroll
        for (int p = 0; p < 2; p++) {   // PT(0): 128 rows x 8 chunks
            int idx = p * NTHR + tid;
            int pr = idx >> 3, pc = idx & 7;
            cp16(sb + PT_B + (uint32_t)(pr * 72 + pc * 8) * 2u,
                 g_PTh + (size_t)pr * DIMN + pc * 8);
        }
        CP_COMMIT();
        #pragma unroll
        for (int p = 0; p < 3; p++) {   // V(0): 64 d-rows x 24 chunks (192 j)
            int idx = p * NTHR + tid;
            int d = idx / 24, c24 = idx % 24;
            cp16(sb + VT_B + (uint32_t)(d * 200 + c24 * 8) * 2u,
                 VTh + (size_t)d * KVROWS + m0 + c24 * 8);
        }
        CP_COMMIT();
    }
    if (tid < 64) Rs[tid] = 0.f;

    float cO[2][4];
    #pragma unroll
    for (int b = 0; b < 2; b++)
        #pragma unroll
        for (int c = 0; c < 4; c++) cO[b][c] = 0.f;
    float rsv[2] = {0.f, 0.f};

    for (int lt = 0; lt < NT; lt++) {
        const int pb = lt & 1;
        const uint32_t* Ksp = (const uint32_t*)(sm + KS_B) + pb * KSZ;
        const uint32_t* Vtp = (const uint32_t*)(sm + VT_B) + pb * VSZ;
        const uint32_t* Ptp = (const uint32_t*)(sm + PT_B) + pb * PSZ;

        CP_WAIT1();
        __syncthreads();   // sync0: K/PT(t) visible

        // ===== S GEMM: content (window 144 per m16 group) + pos (f16 acc) =====
        float cC[5][4];
        uint32_t cP[4][2];
        #pragma unroll
        for (int nb = 0; nb < 5; nb++)
            #pragma unroll
            for (int c = 0; c < 4; c++) cC[nb][c] = 0.f;
        #pragma unroll
        for (int nb = 0; nb < 4; nb++) { cP[nb][0] = 0u; cP[nb][1] = 0u; }

        #pragma unroll
        for (int ks = 0; ks < 4; ks++) {
            const int c2 = ks * 8 + tig;
            const int row = wm * 16 + g;
            uint32_t a[4];
            a[0] = Qsu[row * QS2 + c2];
            a[1] = Qsu[(row + 8) * QS2 + c2];
            a[2] = Qsu[row * QS2 + c2 + 4];
            a[3] = Qsu[(row + 8) * QS2 + c2 + 4];
            #pragma unroll
            for (int nb = 0; nb < 4; nb++) {       // pos: cols wn*32+nb*8
                int n = wn * 32 + nb * 8 + g;
                uint32_t b[2] = { Ptp[n * PT2 + c2], Ptp[n * PT2 + c2 + 4] };
                mma_f16_f16(cP[nb], a, b);
            }
            #pragma unroll
            for (int nb = 0; nb < 5; nb++) {       // content: window blocks
                if (nb < ncnt) {
                    int n = wm * 16 + (nstart + nb) * 8 + g;
                    uint32_t b[2] = { Ksp[n * KS2 + c2], Ksp[n * KS2 + c2 + 4] };
                    mma_f16_f32(cC[nb], a, b);
                }
            }
        }

        // ---- pos scores (f16 pairs) -> posS f32 ----
        #pragma unroll
        for (int nb = 0; nb < 4; nb++) {
            int lp = wn * 32 + nb * 8 + 2 * tig;
            int i1 = wm * 16 + g;
            float2 lo = __half22float2(*(__half2*)&cP[nb][0]);
            float2 hi = __half22float2(*(__half2*)&cP[nb][1]);
            *(float2*)(psf + i1 * PSF + lp)       = lo;
            *(float2*)(psf + (i1 + 8) * PSF + lp) = hi;
        }
        __syncthreads();   // sync_a: posS visible; K/PT(t-1) buffers free

        // prefetch next K + PT into [1-pb]
        if (lt < NT - 1) {
            const int jg0n = m0 + (lt + 1) * BL;
            const uint32_t kdst = sb + KS_B + (uint32_t)(1 - pb) * (KSZ * 4u);
            const uint32_t pdst = sb + PT_B + (uint32_t)(1 - pb) * (PSZ * 4u);
            #pragma unroll
            for (int p = 0; p < 3; p++) {
                int idx = p * NTHR + tid;
                int kr = idx >> 3, kc = idx & 7;
                cp16(kdst + (uint32_t)(kr * 72 + kc * 8) * 2u,
                     Kh + (size_t)(jg0n + kr) * DIMN + kc * 8);
            }
            #pragma unroll
            for (int p = 0; p < 2; p++) {
                int idx = p * NTHR + tid;
                int pr = idx >> 3, pc = idx & 7;
                cp16(pdst + (uint32_t)(pr * 72 + pc * 8) * 2u,
                     g_PTh + (size_t)((lt + 1) * BL + pr) * DIMN + pc * 8);
            }
        }
        CP_COMMIT();

        // ---- exp + windowed W (f16x2) + rowsums ----
        #pragma unroll
        for (int nb = 0; nb < 5; nb++) {
            if (nb < ncnt) {
                int colrel = (nstart + nb) * 8 + 2 * tig;
                #pragma unroll
                for (int h = 0; h < 2; h++) {
                    int ig = g + 8 * h;
                    int i  = wm * 16 + ig;
                    float s0 = cC[nb][2 * h], s1 = cC[nb][2 * h + 1];
                    int l0 = colrel - ig;
                    float w0 = 0.f, w1 = 0.f;
                    if (l0 >= 0 && l0 < 128)
                        w0 = __expf((s0 + psf[i * PSF + l0]) * 0.125f);
                    if (l0 + 1 >= 0 && l0 + 1 < 128)
                        w1 = __expf((s1 + psf[i * PSF + l0 + 1]) * 0.125f);
                    __half2 hw = __floats2half2_rn(w0, w1);
                    float2 bk = __half22float2(hw);
                    rsv[h] += bk.x + bk.y;
                    Wsu[i * WS2 + (colrel >> 1)] = *(uint32_t*)&hw;
                }
            }
        }

        CP_WAIT1();
        __syncthreads();   // sync_b: W visible; V(t) visible

        // ===== PV: per-warp full k-window (144), disjoint 16x16 output =====
        #pragma unroll
        for (int kk = 0; kk < 9; kk++) {
            const int kb2 = kk * 8 + tig;
            const int row = wm * 16 + g;
            uint32_t a[4];
            a[0] = Wsu[row * WS2 + kb2];
            a[1] = Wsu[(row + 8) * WS2 + kb2];
            a[2] = Wsu[row * WS2 + kb2 + 4];
            a[3] = Wsu[(row + 8) * WS2 + kb2 + 4];
            const int jb2 = wm * 8 + kk * 8 + tig;   // abs V j base = wm*16
            #pragma unroll
            for (int nb = 0; nb < 2; nb++) {
                int d = wn * 16 + nb * 8 + g;
                uint32_t b[2] = { Vtp[d * VT2 + jb2], Vtp[d * VT2 + jb2 + 4] };
                mma_f16_f32(cO[nb], a, b);
            }
        }

        // prefetch next V into [1-pb]
        if (lt < NT - 1) {
            const int jg0n = m0 + (lt + 1) * BL;
            const uint32_t vdst = sb + VT_B + (uint32_t)(1 - pb) * (VSZ * 4u);
            #pragma unroll
            for (int p = 0; p < 3; p++) {
                int idx = p * NTHR + tid;
                int d = idx / 24, c24 = idx % 24;
                cp16(vdst + (uint32_t)(d * 200 + c24 * 8) * 2u,
                     VTh + (size_t)d * KVROWS + jg0n + c24 * 8);
            }
        }
        CP_COMMIT();
    }

    // ---- rowsum reduction (cross-wn) ----
    #pragma unroll
    for (int h = 0; h < 2; h++) {
        float v = rsv[h];
        v += __shfl_xor_sync(0xffffffffu, v, 1);
        v += __shfl_xor_sync(0xffffffffu, v, 2);
        if (tig == 0) {
            int i = wm * 16 + g + 8 * h;
            atomicAdd(&Rs[i], v);
        }
    }
    __syncthreads();

    // ---- normalize + store (each warp owns rows wm*16.., cols wn*16..) ----
    {
        int i1 = wm * 16 + g;
        float inv0 = 1.f / Rs[i1];
        float inv1 = 1.f / Rs[i1 + 8];
        #pragma unroll
        for (int nb = 0; nb < 2; nb++) {
            int d = wn * 16 + nb * 8 + 2 * tig;
            float2 o0 = make_float2(cO[nb][0] * inv0, cO[nb][1] * inv0);
            float2 o1 = make_float2(cO[nb][2] * inv1, cO[nb][3] * inv1);
            *(float2*)(O + ((size_t)bh * MSEQ + m0 + i1) * DIMN + d)     = o0;
            *(float2*)(O + ((size_t)bh * MSEQ + m0 + i1 + 8) * DIMN + d) = o1;
        }
    }
}

extern "C" void kernel_launch(void* const* d_in, const int* in_sizes, int n_in,
                              void* d_out, int out_size) {
    const float* Q = (const float*)d_in[0];
    const float* K = (const float*)d_in[1];
    const float* V = (const float*)d_in[2];
    const float* P = (const float*)d_in[3];
    float* O = (float*)d_out;
    (void)n_in; (void)in_sizes; (void)out_size;

    // pre-pass: f32 -> f16 (rna), V and P transposed
    prep_qkv<<<dim3(80, BHN), 256>>>(Q, K, V);
    prep_pt<<<16, 256>>>(P);

    cudaFuncSetAttribute(seqattn_f16_kernel,
                         cudaFuncAttributeMaxDynamicSharedMemorySize, SMEM_BYTES);
    dim3 grid(MSEQ / BM, BHN);   // (16, 64)
    seqattn_f16_kernel<<<grid, NTHR, SMEM_BYTES>>>(O);
}

// round 12
// speedup vs baseline: 1.0763x; 1.0371x over previous
#include <cuda_runtime.h>
#include <cuda_fp16.h>
#include <cstdint>
#include <math.h>

// -------- problem shape --------
#define BHN    64
#define MSEQ   1024
#define DIMN   64
#define LSPAN  1024
#define KVROWS (MSEQ + LSPAN)
#define BM     64
#define BL     128
#define NT     (LSPAN / BL)
#define NTHR   512

// -------- fp16 preconverted operands (device scratch; allocation-free) --------
__device__ __half g_Qh [(size_t)BHN * MSEQ  * DIMN];   //  8 MB, [bh][i][d]
__device__ __half g_Kh [(size_t)BHN * KVROWS * DIMN];  // 16 MB, [bh][j][d]
__device__ __half g_VTh[(size_t)BHN * DIMN * KVROWS];  // 16 MB, [bh][d][j]
__device__ __half g_PTh[(size_t)LSPAN * DIMN];         // 128 KB, [l][d]

// -------- smem byte offsets (double-buffered K/VT/PT) --------
#define QS_B 0                      // Q  [64][72h]        =  9216
#define KS_B 9216                   // K  2x [192][72h]    = 55296
#define VT_B 64512                  // V^T 2x [64][200h]   = 51200
#define PT_B 115712                 // P^T 2x [128][72h]   = 36864
#define WS_B 152576                 // W  [64][200h]       = 25600
#define PS_B 178176                 // posS [64][132] f32  = 33792
#define RS_B 211968                 // rowsums [64] f32    =   256
#define SMEM_BYTES 212224

// buffer sizes in bytes
#define KSZB 27648
#define VSZB 25600
#define PSZB 18432

// -------- strides --------
#define QROWB 144     // Q/K/PT row stride bytes (72 halves)
#define WROWB 400     // W/VT row stride bytes (200 halves)
#define PSF 132       // posS f32 stride

__device__ __forceinline__ uint32_t smem_u32(const void* p) {
    uint32_t a;
    asm("{ .reg .u64 t; cvta.to.shared.u64 t, %1; cvt.u32.u64 %0, t; }" : "=r"(a) : "l"(p));
    return a;
}
__device__ __forceinline__ void cp16(uint32_t dst, const void* src) {
    asm volatile("cp.async.ca.shared.global [%0], [%1], 16;" :: "r"(dst), "l"(src) : "memory");
}
#define CP_COMMIT() asm volatile("cp.async.commit_group;" ::: "memory")
#define CP_WAIT1()  asm volatile("cp.async.wait_group 1;" ::: "memory")

__device__ __forceinline__ void ldsm4(uint32_t r[4], uint32_t a) {
    asm volatile("ldmatrix.sync.aligned.m8n8.x4.shared.b16 {%0,%1,%2,%3}, [%4];"
        : "=r"(r[0]), "=r"(r[1]), "=r"(r[2]), "=r"(r[3]) : "r"(a));
}
__device__ __forceinline__ void ldsm2(uint32_t r[2], uint32_t a) {
    asm volatile("ldmatrix.sync.aligned.m8n8.x2.shared.b16 {%0,%1}, [%2];"
        : "=r"(r[0]), "=r"(r[1]) : "r"(a));
}
__device__ __forceinline__ void stsm2(uint32_t a, uint32_t r0, uint32_t r1) {
    asm volatile("stmatrix.sync.aligned.m8n8.x2.shared.b16 [%0], {%1,%2};"
        :: "r"(a), "r"(r0), "r"(r1) : "memory");
}
__device__ __forceinline__ void mma_f16_f32(float c[4], const uint32_t a[4], const uint32_t b[2]) {
    asm volatile(
        "mma.sync.aligned.m16n8k16.row.col.f32.f16.f16.f32 "
        "{%0,%1,%2,%3}, {%4,%5,%6,%7}, {%8,%9}, {%0,%1,%2,%3};"
        : "+f"(c[0]), "+f"(c[1]), "+f"(c[2]), "+f"(c[3])
        : "r"(a[0]), "r"(a[1]), "r"(a[2]), "r"(a[3]), "r"(b[0]), "r"(b[1]));
}

// ================= pre-pass: f32 -> f16 (rna), V/P transposed =================
__global__ void prep_qkv(const float* __restrict__ Q, const float* __restrict__ K,
                         const float* __restrict__ V) {
    const int x = blockIdx.x, bh = blockIdx.y, tid = threadIdx.x;
    if (x < 16) {
        size_t base = ((size_t)bh * MSEQ + x * 64) * DIMN;
        #pragma unroll
        for (int p = 0; p < 4; p++) {
            int idx = p * 256 + tid;
            float4 v = *(const float4*)(Q + base + (size_t)idx * 4);
            __half2 h0 = __floats2half2_rn(v.x, v.y);
            __half2 h1 = __floats2half2_rn(v.z, v.w);
            *(uint2*)(&g_Qh[base + (size_t)idx * 4]) =
                make_uint2(*(uint32_t*)&h0, *(uint32_t*)&h1);
        }
    } else if (x < 48) {
        size_t base = ((size_t)bh * KVROWS + (x - 16) * 64) * DIMN;
        #pragma unroll
        for (int p = 0; p < 4; p++) {
            int idx = p * 256 + tid;
            float4 v = *(const float4*)(K + base + (size_t)idx * 4);
            __half2 h0 = __floats2half2_rn(v.x, v.y);
            __half2 h1 = __floats2half2_rn(v.z, v.w);
            *(uint2*)(&g_Kh[base + (size_t)idx * 4]) =
                make_uint2(*(uint32_t*)&h0, *(uint32_t*)&h1);
        }
    } else {
        __shared__ float ts[64][65];   // [j][d]
        const int j0 = (x - 48) * 64;
        size_t base = ((size_t)bh * KVROWS + j0) * DIMN;
        #pragma unroll
        for (int p = 0; p < 16; p++) {
            int idx = p * 256 + tid;
            ts[idx >> 6][idx & 63] = V[base + idx];
        }
        __syncthreads();
        const int d = tid >> 2, jq = (tid & 3) * 16;
        uint32_t u[8];
        #pragma unroll
        for (int q = 0; q < 8; q++) {
            __half2 h = __floats2half2_rn(ts[jq + 2 * q][d], ts[jq + 2 * q + 1][d]);
            u[q] = *(uint32_t*)&h;
        }
        __half* dst = &g_VTh[((size_t)bh * DIMN + d) * KVROWS + j0 + jq];
        *(uint4*)dst       = make_uint4(u[0], u[1], u[2], u[3]);
        *(uint4*)(dst + 8) = make_uint4(u[4], u[5], u[6], u[7]);
    }
}

__global__ void prep_pt(const float* __restrict__ P) {
    __shared__ float ts[64][65];   // [l][d]
    const int l0 = blockIdx.x * 64, tid = threadIdx.x;
    #pragma unroll
    for (int p = 0; p < 16; p++) {
        int idx = p * 256 + tid;
        int d = idx >> 6, lq = idx & 63;
        ts[lq][d] = P[(size_t)d * LSPAN + l0 + lq];
    }
    __syncthreads();
    const int lq = tid >> 2, dq = (tid & 3) * 16;
    uint32_t u[8];
    #pragma unroll
    for (int q = 0; q < 8; q++) {
        __half2 h = __floats2half2_rn(ts[lq][dq + 2 * q], ts[lq][dq + 2 * q + 1]);
        u[q] = *(uint32_t*)&h;
    }
    __half* dst = &g_PTh[(size_t)(l0 + lq) * DIMN + dq];
    *(uint4*)dst       = make_uint4(u[0], u[1], u[2], u[3]);
    *(uint4*)(dst + 8) = make_uint4(u[4], u[5], u[6], u[7]);
}

// ================= main kernel: LDSM/STSM fragments, m16 windows =================
__global__ void __launch_bounds__(NTHR, 1) seqattn_f16_kernel(float* __restrict__ O) {
    extern __shared__ char sm[];
    const uint32_t sb = smem_u32(sm);

    float* psf = (float*)(sm + PS_B);
    float* Rs  = (float*)(sm + RS_B);

    const int tid  = threadIdx.x;
    const int w    = tid >> 5;
    const int lane = tid & 31;
    const int g    = lane >> 2;
    const int tig  = lane & 3;

    // 16 warps = 4 m-groups x 4 n-warps
    const int wm = w >> 2;
    const int wn = w & 3;
    // content window: 18 blocks of 8 cols; wn gets {5,5,4,4}
    const int nstart = (wn < 2) ? wn * 5 : 10 + (wn - 2) * 4;
    const int ncnt   = (wn < 2) ? 5 : 4;

    // LDSM lane addressing helpers
    const int lr = lane & 15;            // row-in-16
    const int lk = lane >> 4;            // k-half (16B units)
    const int q4 = lane >> 3;            // x4 quadrant
    const int rr = lane & 7;             // row-in-8

    const int bh = blockIdx.y;
    const int m0 = blockIdx.x * BM;

    const __half* Qh  = g_Qh  + ((size_t)bh * MSEQ + m0) * DIMN;
    const __half* Kh  = g_Kh  + (size_t)bh * KVROWS * DIMN;
    const __half* VTh = g_VTh + (size_t)bh * DIMN * KVROWS;

    // ---- preamble: Q + K(0) + PT(0) (group0), V(0) (group1) ----
    {
        int r = tid >> 3, c = tid & 7;
        cp16(sb + QS_B + (uint32_t)(r * 72 + c * 8) * 2u, Qh + (size_t)r * DIMN + c * 8);
        #pragma unroll
        for (int p = 0; p < 3; p++) {
            int idx = p * NTHR + tid;
            int kr = idx >> 3, kc = idx & 7;
            cp16(sb + KS_B + (uint32_t)(kr * 72 + kc * 8) * 2u,
                 Kh + (size_t)(m0 + kr) * DIMN + kc * 8);
        }
        #pragma unroll
        for (int p = 0; p < 2; p++) {
            int idx = p * NTHR + tid;
            int pr = idx >> 3, pc = idx & 7;
            cp16(sb + PT_B + (uint32_t)(pr * 72 + pc * 8) * 2u,
                 g_PTh + (size_t)pr * DIMN + pc * 8);
        }
        CP_COMMIT();
        #pragma unroll
        for (int p = 0; p < 3; p++) {
            int idx = p * NTHR + tid;
            int d = idx / 24, c24 = idx % 24;
            cp16(sb + VT_B + (uint32_t)(d * 200 + c24 * 8) * 2u,
                 VTh + (size_t)d * KVROWS + m0 + c24 * 8);
        }
        CP_COMMIT();
    }
    if (tid < 64) Rs[tid] = 0.f;

    // lane-constant fragment base addresses
    const uint32_t aQbase = sb + QS_B + (uint32_t)((wm * 16 + lr) * QROWB + lk * 16);
    const uint32_t aWbase = sb + WS_B + (uint32_t)((wm * 16 + lr) * WROWB + lk * 16);
    const uint32_t sWbase = sb + WS_B + (uint32_t)((wm * 16 + lr) * WROWB);
    // B x4 lane pattern offsets
    const uint32_t bRow = (uint32_t)(((q4 >> 1) * 8 + rr) * QROWB + (q4 & 1) * 16);
    const uint32_t vRow = (uint32_t)(((q4 >> 1) * 8 + rr) * WROWB + (q4 & 1) * 16);
    // B x2 lane pattern (lanes 0-15 meaningful)
    const uint32_t bRow2 = (uint32_t)(rr * QROWB + ((lane >> 3) & 1) * 16);

    float cO[2][4];
    #pragma unroll
    for (int b = 0; b < 2; b++)
        #pragma unroll
        for (int c = 0; c < 4; c++) cO[b][c] = 0.f;
    float rsv[2] = {0.f, 0.f};

    for (int lt = 0; lt < NT; lt++) {
        const int pb = lt & 1;
        const uint32_t ksOff = sb + KS_B + (uint32_t)pb * KSZB;
        const uint32_t vtOff = sb + VT_B + (uint32_t)pb * VSZB;
        const uint32_t ptOff = sb + PT_B + (uint32_t)pb * PSZB;

        CP_WAIT1();
        __syncthreads();   // sync0: K/PT(t) visible

        // ===== S GEMM: content (144-window) f32acc + pos f32acc =====
        float cC[5][4], cP[4][4];
        #pragma unroll
        for (int nb = 0; nb < 5; nb++)
            #pragma unroll
            for (int c = 0; c < 4; c++) cC[nb][c] = 0.f;
        #pragma unroll
        for (int nb = 0; nb < 4; nb++)
            #pragma unroll
            for (int c = 0; c < 4; c++) cP[nb][c] = 0.f;

        #pragma unroll
        for (int ks = 0; ks < 4; ks++) {
            uint32_t a[4];
            ldsm4(a, aQbase + ks * 32);
            #pragma unroll
            for (int pp = 0; pp < 2; pp++) {      // pos: 2 x4 = 4 blocks
                uint32_t bb[4];
                ldsm4(bb, ptOff + (uint32_t)((wn * 32 + pp * 16) * QROWB) + bRow + ks * 32);
                mma_f16_f32(cP[pp * 2],     a, bb);
                mma_f16_f32(cP[pp * 2 + 1], a, bb + 2);
            }
            #pragma unroll
            for (int pp = 0; pp < 2; pp++) {      // content: 2 x4 = 4 blocks
                uint32_t bb[4];
                ldsm4(bb, ksOff + (uint32_t)((wm * 16 + (nstart + pp * 2) * 8) * QROWB) + bRow + ks * 32);
                mma_f16_f32(cC[pp * 2],     a, bb);
                mma_f16_f32(cC[pp * 2 + 1], a, bb + 2);
            }
            if (wn < 2) {                          // 5th content block (x2)
                uint32_t b2[2];
                ldsm2(b2, ksOff + (uint32_t)((wm * 16 + (nstart + 4) * 8) * QROWB) + bRow2 + ks * 32);
                mma_f16_f32(cC[4], a, b2);
            }
        }

        // ---- pos scores -> posS (f32) ----
        #pragma unroll
        for (int nb = 0; nb < 4; nb++) {
            int lp = wn * 32 + nb * 8 + 2 * tig;
            int i1 = wm * 16 + g;
            *(float2*)(psf + i1 * PSF + lp)       = make_float2(cP[nb][0], cP[nb][1]);
            *(float2*)(psf + (i1 + 8) * PSF + lp) = make_float2(cP[nb][2], cP[nb][3]);
        }
        __syncthreads();   // sync_a: posS visible; K/PT(t-1) free

        // prefetch next K + PT into [1-pb]
        if (lt < NT - 1) {
            const int jg0n = m0 + (lt + 1) * BL;
            const uint32_t kdst = sb + KS_B + (uint32_t)(1 - pb) * KSZB;
            const uint32_t pdst = sb + PT_B + (uint32_t)(1 - pb) * PSZB;
            #pragma unroll
            for (int p = 0; p < 3; p++) {
                int idx = p * NTHR + tid;
                int kr = idx >> 3, kc = idx & 7;
                cp16(kdst + (uint32_t)(kr * 72 + kc * 8) * 2u,
                     Kh + (size_t)(jg0n + kr) * DIMN + kc * 8);
            }
            #pragma unroll
            for (int p = 0; p < 2; p++) {
                int idx = p * NTHR + tid;
                int pr = idx >> 3, pc = idx & 7;
                cp16(pdst + (uint32_t)(pr * 72 + pc * 8) * 2u,
                     g_PTh + (size_t)((lt + 1) * BL + pr) * DIMN + pc * 8);
            }
        }
        CP_COMMIT();

        // ---- exp + windowed W via stmatrix + rowsums ----
        #pragma unroll
        for (int nb = 0; nb < 5; nb++) {
            if (nb < ncnt) {
                int colrel = (nstart + nb) * 8 + 2 * tig;
                uint32_t hw2[2];
                #pragma unroll
                for (int h = 0; h < 2; h++) {
                    int ig = g + 8 * h;
                    int i  = wm * 16 + ig;
                    float s0 = cC[nb][2 * h], s1 = cC[nb][2 * h + 1];
                    int l0 = colrel - ig;
                    float w0 = 0.f, w1 = 0.f;
                    if (l0 >= 0 && l0 < 128)
                        w0 = __expf((s0 + psf[i * PSF + l0]) * 0.125f);
                    if (l0 + 1 >= 0 && l0 + 1 < 128)
                        w1 = __expf((s1 + psf[i * PSF + l0 + 1]) * 0.125f);
                    __half2 hw = __floats2half2_rn(w0, w1);
                    float2 bk = __half22float2(hw);
                    rsv[h] += bk.x + bk.y;
                    hw2[h] = *(uint32_t*)&hw;
                }
                stsm2(sWbase + (uint32_t)((nstart + nb) * 16), hw2[0], hw2[1]);
            }
        }

        CP_WAIT1();
        __syncthreads();   // sync_b: W visible; V(t) visible

        // ===== PV: per-warp 144-k window, disjoint 16x16 output =====
        #pragma unroll
        for (int kk = 0; kk < 9; kk++) {
            uint32_t a[4];
            ldsm4(a, aWbase + kk * 32);
            uint32_t bv[4];
            ldsm4(bv, vtOff + (uint32_t)(wn * 16 * WROWB) + vRow + (uint32_t)(wm * 32 + kk * 32));
            mma_f16_f32(cO[0], a, bv);
            mma_f16_f32(cO[1], a, bv + 2);
        }

        // prefetch next V into [1-pb]
        if (lt < NT - 1) {
            const int jg0n = m0 + (lt + 1) * BL;
            const uint32_t vdst = sb + VT_B + (uint32_t)(1 - pb) * VSZB;
            #pragma unroll
            for (int p = 0; p < 3; p++) {
                int idx = p * NTHR + tid;
                int d = idx / 24, c24 = idx % 24;
                cp16(vdst + (uint32_t)(d * 200 + c24 * 8) * 2u,
                     VTh + (size_t)d * KVROWS + jg0n + c24 * 8);
            }
        }
        CP_COMMIT();
    }

    // ---- rowsum reduction (cross-wn) ----
    #pragma unroll
    for (int h = 0; h < 2; h++) {
        float v = rsv[h];
        v += __shfl_xor_sync(0xffffffffu, v, 1);
        v += __shfl_xor_sync(0xffffffffu, v, 2);
        if (tig == 0) {
            int i = wm * 16 + g + 8 * h;
            atomicAdd(&Rs[i], v);
        }
    }
    __syncthreads();

    // ---- normalize + store (warp owns rows wm*16.., cols wn*16..) ----
    {
        int i1 = wm * 16 + g;
        float inv0 = 1.f / Rs[i1];
        float inv1 = 1.f / Rs[i1 + 8];
        #pragma unroll
        for (int nb = 0; nb < 2; nb++) {
            int d = wn * 16 + nb * 8 + 2 * tig;
            float2 o0 = make_float2(cO[nb][0] * inv0, cO[nb][1] * inv0);
            float2 o1 = make_float2(cO[nb][2] * inv1, cO[nb][3] * inv1);
            *(float2*)(O + ((size_t)bh * MSEQ + m0 + i1) * DIMN + d)     = o0;
            *(float2*)(O + ((size_t)bh * MSEQ + m0 + i1 + 8) * DIMN + d) = o1;
        }
    }
}

extern "C" void kernel_launch(void* const* d_in, const int* in_sizes, int n_in,
                              void* d_out, int out_size) {
    const float* Q = (const float*)d_in[0];
    const float* K = (const float*)d_in[1];
    const float* V = (const float*)d_in[2];
    const float* P = (const float*)d_in[3];
    float* O = (float*)d_out;
    (void)n_in; (void)in_sizes; (void)out_size;

    prep_qkv<<<dim3(80, BHN), 256>>>(Q, K, V);
    prep_pt<<<16, 256>>>(P);

    cudaFuncSetAttribute(seqattn_f16_kernel,
                         cudaFuncAttributeMaxDynamicSharedMemorySize, SMEM_BYTES);
    dim3 grid(MSEQ / BM, BHN);   // (16, 64)
    seqattn_f16_kernel<<<grid, NTHR, SMEM_BYTES>>>(O);
}

// round 14
// speedup vs baseline: 1.0813x; 1.0047x over previous
#include <cuda_runtime.h>
#include <cuda_fp16.h>
#include <cstdint>
#include <math.h>

// -------- problem shape --------
#define BHN    64
#define MSEQ   1024
#define DIMN   64
#define LSPAN  1024
#define KVROWS (MSEQ + LSPAN)
#define BM     64
#define BL     128
#define NT     (LSPAN / BL)
#define NTHR   512

// -------- fp16 preconverted operands (device scratch; allocation-free) --------
__device__ __half g_Qh [(size_t)BHN * MSEQ  * DIMN];   //  8 MB, [bh][i][d]
__device__ __half g_Kh [(size_t)BHN * KVROWS * DIMN];  // 16 MB, [bh][j][d]
__device__ __half g_VTh[(size_t)BHN * DIMN * KVROWS];  // 16 MB, [bh][d][j]
__device__ __half g_PTh[(size_t)LSPAN * DIMN];         // 128 KB, [l][d]

// -------- smem byte offsets (double-buffered K/VT/PT) --------
#define QS_B 0                      // Q  [64][72h]        =  9216
#define KS_B 9216                   // K  2x [192][72h]    = 55296
#define VT_B 64512                  // V^T 2x [64][200h]   = 51200
#define PT_B 115712                 // P^T 2x [128][72h]   = 36864
#define WS_B 152576                 // W  [64][200h]       = 25600
#define PS_B 178176                 // posS [64][132] f32  = 33792
#define RS_B 211968                 // rowsums [64] f32    =   256
#define SMEM_BYTES 212224

// buffer sizes in bytes
#define KSZB 27648
#define VSZB 25600
#define PSZB 18432

// -------- strides --------
#define QROWB 144     // Q/K/PT row stride bytes (72 halves)
#define WROWB 400     // W/VT row stride bytes (200 halves)
#define PSF 132       // posS f32 stride (EVEN — float2 stores need 8B alignment)

__device__ __forceinline__ uint32_t smem_u32(const void* p) {
    uint32_t a;
    asm("{ .reg .u64 t; cvta.to.shared.u64 t, %1; cvt.u32.u64 %0, t; }" : "=r"(a) : "l"(p));
    return a;
}
__device__ __forceinline__ void cp16(uint32_t dst, const void* src) {
    asm volatile("cp.async.ca.shared.global [%0], [%1], 16;" :: "r"(dst), "l"(src) : "memory");
}
#define CP_COMMIT() asm volatile("cp.async.commit_group;" ::: "memory")
#define CP_WAIT0()  asm volatile("cp.async.wait_group 0;" ::: "memory")
#define BAR_GRP(id) asm volatile("bar.sync %0, 128;" :: "r"(id) : "memory")

__device__ __forceinline__ void ldsm4(uint32_t r[4], uint32_t a) {
    asm volatile("ldmatrix.sync.aligned.m8n8.x4.shared.b16 {%0,%1,%2,%3}, [%4];"
        : "=r"(r[0]), "=r"(r[1]), "=r"(r[2]), "=r"(r[3]) : "r"(a));
}
__device__ __forceinline__ void ldsm2(uint32_t r[2], uint32_t a) {
    asm volatile("ldmatrix.sync.aligned.m8n8.x2.shared.b16 {%0,%1}, [%2];"
        : "=r"(r[0]), "=r"(r[1]) : "r"(a));
}
__device__ __forceinline__ void stsm2(uint32_t a, uint32_t r0, uint32_t r1) {
    asm volatile("stmatrix.sync.aligned.m8n8.x2.shared.b16 [%0], {%1,%2};"
        :: "r"(a), "r"(r0), "r"(r1) : "memory");
}
__device__ __forceinline__ void mma_f16_f32(float c[4], const uint32_t a[4], const uint32_t b[2]) {
    asm volatile(
        "mma.sync.aligned.m16n8k16.row.col.f32.f16.f16.f32 "
        "{%0,%1,%2,%3}, {%4,%5,%6,%7}, {%8,%9}, {%0,%1,%2,%3};"
        : "+f"(c[0]), "+f"(c[1]), "+f"(c[2]), "+f"(c[3])
        : "r"(a[0]), "r"(a[1]), "r"(a[2]), "r"(a[3]), "r"(b[0]), "r"(b[1]));
}

// ================= pre-pass: f32 -> f16 (rna), V/P transposed =================
__global__ void prep_qkv(const float* __restrict__ Q, const float* __restrict__ K,
                         const float* __restrict__ V) {
    const int x = blockIdx.x, bh = blockIdx.y, tid = threadIdx.x;
    if (x < 16) {
        size_t base = ((size_t)bh * MSEQ + x * 64) * DIMN;
        #pragma unroll
        for (int p = 0; p < 4; p++) {
            int idx = p * 256 + tid;
            float4 v = *(const float4*)(Q + base + (size_t)idx * 4);
            __half2 h0 = __floats2half2_rn(v.x, v.y);
            __half2 h1 = __floats2half2_rn(v.z, v.w);
            *(uint2*)(&g_Qh[base + (size_t)idx * 4]) =
                make_uint2(*(uint32_t*)&h0, *(uint32_t*)&h1);
        }
    } else if (x < 48) {
        size_t base = ((size_t)bh * KVROWS + (x - 16) * 64) * DIMN;
        #pragma unroll
        for (int p = 0; p < 4; p++) {
            int idx = p * 256 + tid;
            float4 v = *(const float4*)(K + base + (size_t)idx * 4);
            __half2 h0 = __floats2half2_rn(v.x, v.y);
            __half2 h1 = __floats2half2_rn(v.z, v.w);
            *(uint2*)(&g_Kh[base + (size_t)idx * 4]) =
                make_uint2(*(uint32_t*)&h0, *(uint32_t*)&h1);
        }
    } else {
        __shared__ float ts[64][65];   // [j][d]
        const int j0 = (x - 48) * 64;
        size_t base = ((size_t)bh * KVROWS + j0) * DIMN;
        #pragma unroll
        for (int p = 0; p < 16; p++) {
            int idx = p * 256 + tid;
            ts[idx >> 6][idx & 63] = V[base + idx];
        }
        __syncthreads();
        const int d = tid >> 2, jq = (tid & 3) * 16;
        uint32_t u[8];
        #pragma unroll
        for (int q = 0; q < 8; q++) {
            __half2 h = __floats2half2_rn(ts[jq + 2 * q][d], ts[jq + 2 * q + 1][d]);
            u[q] = *(uint32_t*)&h;
        }
        __half* dst = &g_VTh[((size_t)bh * DIMN + d) * KVROWS + j0 + jq];
        *(uint4*)dst       = make_uint4(u[0], u[1], u[2], u[3]);
        *(uint4*)(dst + 8) = make_uint4(u[4], u[5], u[6], u[7]);
    }
}

__global__ void prep_pt(const float* __restrict__ P) {
    __shared__ float ts[64][65];   // [l][d]
    const int l0 = blockIdx.x * 64, tid = threadIdx.x;
    #pragma unroll
    for (int p = 0; p < 16; p++) {
        int idx = p * 256 + tid;
        int d = idx >> 6, lq = idx & 63;
        ts[lq][d] = P[(size_t)d * LSPAN + l0 + lq];
    }
    __syncthreads();
    const int lq = tid >> 2, dq = (tid & 3) * 16;
    uint32_t u[8];
    #pragma unroll
    for (int q = 0; q < 8; q++) {
        __half2 h = __floats2half2_rn(ts[lq][dq + 2 * q], ts[lq][dq + 2 * q + 1]);
        u[q] = *(uint32_t*)&h;
    }
    __half* dst = &g_PTh[(size_t)(l0 + lq) * DIMN + dq];
    *(uint4*)dst       = make_uint4(u[0], u[1], u[2], u[3]);
    *(uint4*)(dst + 8) = make_uint4(u[4], u[5], u[6], u[7]);
}

// ============ main kernel: per-m16-group named barriers, hoisted Q ============
__global__ void __launch_bounds__(NTHR, 1) seqattn_f16_kernel(float* __restrict__ O) {
    extern __shared__ char sm[];
    const uint32_t sb = smem_u32(sm);

    float* psf = (float*)(sm + PS_B);
    float* Rs  = (float*)(sm + RS_B);

    const int tid  = threadIdx.x;
    const int w    = tid >> 5;
    const int lane = tid & 31;
    const int g    = lane >> 2;
    const int tig  = lane & 3;

    // 16 warps = 4 m-groups x 4 n-warps
    const int wm = w >> 2;
    const int wn = w & 3;
    // content window: 18 blocks of 8 cols; wn gets {5,5,4,4}
    const int nstart = (wn < 2) ? wn * 5 : 10 + (wn - 2) * 4;
    const int ncnt   = (wn < 2) ? 5 : 4;
    const int barid  = wm + 1;

    // LDSM lane addressing helpers
    const int lr = lane & 15;
    const int lk = lane >> 4;
    const int q4 = lane >> 3;
    const int rr = lane & 7;

    const int bh = blockIdx.y;
    const int m0 = blockIdx.x * BM;

    const __half* Qh  = g_Qh  + ((size_t)bh * MSEQ + m0) * DIMN;
    const __half* Kh  = g_Kh  + (size_t)bh * KVROWS * DIMN;
    const __half* VTh = g_VTh + (size_t)bh * DIMN * KVROWS;

    // ---- preamble: issue Q + K(0) + PT(0) + V(0), single commit group ----
    {
        int r = tid >> 3, c = tid & 7;
        cp16(sb + QS_B + (uint32_t)(r * 72 + c * 8) * 2u, Qh + (size_t)r * DIMN + c * 8);
        #pragma unroll
        for (int p = 0; p < 3; p++) {
            int idx = p * NTHR + tid;
            int kr = idx >> 3, kc = idx & 7;
            cp16(sb + KS_B + (uint32_t)(kr * 72 + kc * 8) * 2u,
                 Kh + (size_t)(m0 + kr) * DIMN + kc * 8);
        }
        #pragma unroll
        for (int p = 0; p < 2; p++) {
            int idx = p * NTHR + tid;
            int pr = idx >> 3, pc = idx & 7;
            cp16(sb + PT_B + (uint32_t)(pr * 72 + pc * 8) * 2u,
                 g_PTh + (size_t)pr * DIMN + pc * 8);
        }
        #pragma unroll
        for (int p = 0; p < 3; p++) {
            int idx = p * NTHR + tid;
            int d = idx / 24, c24 = idx % 24;
            cp16(sb + VT_B + (uint32_t)(d * 200 + c24 * 8) * 2u,
                 VTh + (size_t)d * KVROWS + m0 + c24 * 8);
        }
        CP_COMMIT();
    }
    if (tid < 64) Rs[tid] = 0.f;

    // lane-constant fragment base addresses
    const uint32_t aQbase = sb + QS_B + (uint32_t)((wm * 16 + lr) * QROWB + lk * 16);
    const uint32_t aWbase = sb + WS_B + (uint32_t)((wm * 16 + lr) * WROWB + lk * 16);
    const uint32_t sWbase = sb + WS_B + (uint32_t)((wm * 16 + lr) * WROWB);
    const uint32_t bRow = (uint32_t)(((q4 >> 1) * 8 + rr) * QROWB + (q4 & 1) * 16);
    const uint32_t vRow = (uint32_t)(((q4 >> 1) * 8 + rr) * WROWB + (q4 & 1) * 16);
    const uint32_t bRow2 = (uint32_t)(rr * QROWB + ((lane >> 3) & 1) * 16);

    CP_WAIT0();
    __syncthreads();

    // ---- hoist Q fragments (tile-invariant) ----
    uint32_t aq[4][4];
    #pragma unroll
    for (int ks = 0; ks < 4; ks++) ldsm4(aq[ks], aQbase + ks * 32);

    float cO[2][4];
    #pragma unroll
    for (int b = 0; b < 2; b++)
        #pragma unroll
        for (int c = 0; c < 4; c++) cO[b][c] = 0.f;
    float rsv[2] = {0.f, 0.f};

    for (int lt = 0; lt < NT; lt++) {
        const int pb = lt & 1;
        const uint32_t ksOff = sb + KS_B + (uint32_t)pb * KSZB;
        const uint32_t vtOff = sb + VT_B + (uint32_t)pb * VSZB;
        const uint32_t ptOff = sb + PT_B + (uint32_t)pb * PSZB;

        if (lt > 0) { CP_WAIT0(); __syncthreads(); }   // tile(t) ready; all groups done with t-1

        // ---- issue ALL prefetches for tile t+1 immediately (into 1-pb) ----
        if (lt < NT - 1) {
            const int jg0n = m0 + (lt + 1) * BL;
            const uint32_t kdst = sb + KS_B + (uint32_t)(1 - pb) * KSZB;
            const uint32_t pdst = sb + PT_B + (uint32_t)(1 - pb) * PSZB;
            const uint32_t vdst = sb + VT_B + (uint32_t)(1 - pb) * VSZB;
            #pragma unroll
            for (int p = 0; p < 3; p++) {
                int idx = p * NTHR + tid;
                int kr = idx >> 3, kc = idx & 7;
                cp16(kdst + (uint32_t)(kr * 72 + kc * 8) * 2u,
                     Kh + (size_t)(jg0n + kr) * DIMN + kc * 8);
            }
            #pragma unroll
            for (int p = 0; p < 2; p++) {
                int idx = p * NTHR + tid;
                int pr = idx >> 3, pc = idx & 7;
                cp16(pdst + (uint32_t)(pr * 72 + pc * 8) * 2u,
                     g_PTh + (size_t)((lt + 1) * BL + pr) * DIMN + pc * 8);
            }
            #pragma unroll
            for (int p = 0; p < 3; p++) {
                int idx = p * NTHR + tid;
                int d = idx / 24, c24 = idx % 24;
                cp16(vdst + (uint32_t)(d * 200 + c24 * 8) * 2u,
                     VTh + (size_t)d * KVROWS + jg0n + c24 * 8);
            }
        }
        CP_COMMIT();

        // ===== S GEMM: content (144-window) + pos, f32 acc =====
        float cC[5][4], cP[4][4];
        #pragma unroll
        for (int nb = 0; nb < 5; nb++)
            #pragma unroll
            for (int c = 0; c < 4; c++) cC[nb][c] = 0.f;
        #pragma unroll
        for (int nb = 0; nb < 4; nb++)
            #pragma unroll
            for (int c = 0; c < 4; c++) cP[nb][c] = 0.f;

        #pragma unroll
        for (int ks = 0; ks < 4; ks++) {
            #pragma unroll
            for (int pp = 0; pp < 2; pp++) {      // pos: 2 x4 = 4 blocks
                uint32_t bb[4];
                ldsm4(bb, ptOff + (uint32_t)((wn * 32 + pp * 16) * QROWB) + bRow + ks * 32);
                mma_f16_f32(cP[pp * 2],     aq[ks], bb);
                mma_f16_f32(cP[pp * 2 + 1], aq[ks], bb + 2);
            }
            #pragma unroll
            for (int pp = 0; pp < 2; pp++) {      // content: 2 x4 = 4 blocks
                uint32_t bb[4];
                ldsm4(bb, ksOff + (uint32_t)((wm * 16 + (nstart + pp * 2) * 8) * QROWB) + bRow + ks * 32);
                mma_f16_f32(cC[pp * 2],     aq[ks], bb);
                mma_f16_f32(cC[pp * 2 + 1], aq[ks], bb + 2);
            }
            if (wn < 2) {                          // 5th content block (x2)
                uint32_t b2[2];
                ldsm2(b2, ksOff + (uint32_t)((wm * 16 + (nstart + 4) * 8) * QROWB) + bRow2 + ks * 32);
                mma_f16_f32(cC[4], aq[ks], b2);
            }
        }

        // ---- pos scores -> posS (f32), group-local visibility ----
        #pragma unroll
        for (int nb = 0; nb < 4; nb++) {
            int lp = wn * 32 + nb * 8 + 2 * tig;
            int i1 = wm * 16 + g;
            *(float2*)(psf + i1 * PSF + lp)       = make_float2(cP[nb][0], cP[nb][1]);
            *(float2*)(psf + (i1 + 8) * PSF + lp) = make_float2(cP[nb][2], cP[nb][3]);
        }
        BAR_GRP(barid);   // posS visible within m-group

        // ---- exp + windowed W via stmatrix + rowsums ----
        #pragma unroll
        for (int nb = 0; nb < 5; nb++) {
            if (nb < ncnt) {
                int colrel = (nstart + nb) * 8 + 2 * tig;
                uint32_t hw2[2];
                #pragma unroll
                for (int h = 0; h < 2; h++) {
                    int ig = g + 8 * h;
                    int i  = wm * 16 + ig;
                    float s0 = cC[nb][2 * h], s1 = cC[nb][2 * h + 1];
                    int l0 = colrel - ig;
                    float w0 = 0.f, w1 = 0.f;
                    if (l0 >= 0 && l0 < 128)
                        w0 = __expf((s0 + psf[i * PSF + l0]) * 0.125f);
                    if (l0 + 1 >= 0 && l0 + 1 < 128)
                        w1 = __expf((s1 + psf[i * PSF + l0 + 1]) * 0.125f);
                    __half2 hw = __floats2half2_rn(w0, w1);
                    float2 bk = __half22float2(hw);
                    rsv[h] += bk.x + bk.y;
                    hw2[h] = *(uint32_t*)&hw;
                }
                stsm2(sWbase + (uint32_t)((nstart + nb) * 16), hw2[0], hw2[1]);
            }
        }
        BAR_GRP(barid);   // W rows of this m-group visible

        // ===== PV: per-warp 144-k window, disjoint 16x16 output =====
        #pragma unroll
        for (int kk = 0; kk < 9; kk++) {
            uint32_t a[4];
            ldsm4(a, aWbase + kk * 32);
            uint32_t bv[4];
            ldsm4(bv, vtOff + (uint32_t)(wn * 16 * WROWB) + vRow + (uint32_t)(wm * 32 + kk * 32));
            mma_f16_f32(cO[0], a, bv);
            mma_f16_f32(cO[1], a, bv + 2);
        }
    }

    // ---- rowsum reduction (cross-wn) ----
    __syncthreads();
    #pragma unroll
    for (int h = 0; h < 2; h++) {
        float v = rsv[h];
        v += __shfl_xor_sync(0xffffffffu, v, 1);
        v += __shfl_xor_sync(0xffffffffu, v, 2);
        if (tig == 0) {
            int i = wm * 16 + g + 8 * h;
            atomicAdd(&Rs[i], v);
        }
    }
    __syncthreads();

    // ---- normalize + store (warp owns rows wm*16.., cols wn*16..) ----
    {
        int i1 = wm * 16 + g;
        float inv0 = 1.f / Rs[i1];
        float inv1 = 1.f / Rs[i1 + 8];
        #pragma unroll
        for (int nb = 0; nb < 2; nb++) {
            int d = wn * 16 + nb * 8 + 2 * tig;
            float2 o0 = make_float2(cO[nb][0] * inv0, cO[nb][1] * inv0);
            float2 o1 = make_float2(cO[nb][2] * inv1, cO[nb][3] * inv1);
            *(float2*)(O + ((size_t)bh * MSEQ + m0 + i1) * DIMN + d)     = o0;
            *(float2*)(O + ((size_t)bh * MSEQ + m0 + i1 + 8) * DIMN + d) = o1;
        }
    }
}

extern "C" void kernel_launch(void* const* d_in, const int* in_sizes, int n_in,
                              void* d_out, int out_size) {
    const float* Q = (const float*)d_in[0];
    const float* K = (const float*)d_in[1];
    const float* V = (const float*)d_in[2];
    const float* P = (const float*)d_in[3];
    float* O = (float*)d_out;
    (void)n_in; (void)in_sizes; (void)out_size;

    // prep order chosen so ncu -s 5 lands on the main kernel
    prep_pt<<<16, 256>>>(P);
    prep_qkv<<<dim3(80, BHN), 256>>>(Q, K, V);

    cudaFuncSetAttribute(seqattn_f16_kernel,
                         cudaFuncAttributeMaxDynamicSharedMemorySize, SMEM_BYTES);
    dim3 grid(MSEQ / BM, BHN);   // (16, 64)
    seqattn_f16_kernel<<<grid, NTHR, SMEM_BYTES>>>(O);
}

// round 15
// speedup vs baseline: 1.2151x; 1.1237x over previous
#include <cuda_runtime.h>
#include <cuda_fp16.h>
#include <cstdint>
#include <math.h>

// -------- problem shape --------
#define BHN    64
#define MSEQ   1024
#define DIMN   64
#define LSPAN  1024
#define KVROWS (MSEQ + LSPAN)
#define BM     64
#define BL     128
#define NT     (LSPAN / BL)
#define NTHR   512

// -------- fp16 preconverted operands (device scratch; allocation-free) --------
__device__ __half g_Qh [(size_t)BHN * MSEQ  * DIMN];   //  8 MB, [bh][i][d]  (pre-scaled x0.125)
__device__ __half g_Kh [(size_t)BHN * KVROWS * DIMN];  // 16 MB, [bh][j][d]
__device__ __half g_VTh[(size_t)BHN * DIMN * KVROWS];  // 16 MB, [bh][d][j]
__device__ __half g_PTh[(size_t)LSPAN * DIMN];         // 128 KB, [l][d]

// -------- smem byte offsets (double-buffered K/VT/PT, single W/posS) --------
#define QS_B 0                      // Q  [64][72h]        =  9216
#define KS_B 9216                   // K  2x [192][72h]    = 55296
#define VT_B 64512                  // V^T 2x [64][200h]   = 51200
#define PT_B 115712                 // P^T 2x [128][72h]   = 36864
#define WS_B 152576                 // W  [64][200h]       = 25600
#define PS_B 178176                 // posS [64][132] f32  = 33792
#define RS_B 211968                 // rowsums [64] f32    =   256
#define SMEM_BYTES 212224

// buffer sizes in bytes
#define KSZB 27648
#define VSZB 25600
#define PSZB 18432

// -------- strides --------
#define QROWB 144     // Q/K/PT row stride bytes (72 halves)
#define WROWB 400     // W/VT row stride bytes (200 halves)
#define PSF 132       // posS f32 stride (EVEN — float2 stores)

#define LOG2E_F 1.4426950408889634f

__device__ __forceinline__ uint32_t smem_u32(const void* p) {
    uint32_t a;
    asm("{ .reg .u64 t; cvta.to.shared.u64 t, %1; cvt.u32.u64 %0, t; }" : "=r"(a) : "l"(p));
    return a;
}
__device__ __forceinline__ void cp16(uint32_t dst, const void* src) {
    asm volatile("cp.async.ca.shared.global [%0], [%1], 16;" :: "r"(dst), "l"(src) : "memory");
}
#define CP_COMMIT() asm volatile("cp.async.commit_group;" ::: "memory")
#define CP_WAIT1()  asm volatile("cp.async.wait_group 1;" ::: "memory")
#define BAR_GRP(id) asm volatile("bar.sync %0, 128;" :: "r"(id) : "memory")

__device__ __forceinline__ void ldsm4(uint32_t r[4], uint32_t a) {
    asm volatile("ldmatrix.sync.aligned.m8n8.x4.shared.b16 {%0,%1,%2,%3}, [%4];"
        : "=r"(r[0]), "=r"(r[1]), "=r"(r[2]), "=r"(r[3]) : "r"(a));
}
__device__ __forceinline__ void ldsm2(uint32_t r[2], uint32_t a) {
    asm volatile("ldmatrix.sync.aligned.m8n8.x2.shared.b16 {%0,%1}, [%2];"
        : "=r"(r[0]), "=r"(r[1]) : "r"(a));
}
__device__ __forceinline__ void stsm2(uint32_t a, uint32_t r0, uint32_t r1) {
    asm volatile("stmatrix.sync.aligned.m8n8.x2.shared.b16 [%0], {%1,%2};"
        :: "r"(a), "r"(r0), "r"(r1) : "memory");
}
__device__ __forceinline__ void mma_f16_f32(float c[4], const uint32_t a[4], const uint32_t b[2]) {
    asm volatile(
        "mma.sync.aligned.m16n8k16.row.col.f32.f16.f16.f32 "
        "{%0,%1,%2,%3}, {%4,%5,%6,%7}, {%8,%9}, {%0,%1,%2,%3};"
        : "+f"(c[0]), "+f"(c[1]), "+f"(c[2]), "+f"(c[3])
        : "r"(a[0]), "r"(a[1]), "r"(a[2]), "r"(a[3]), "r"(b[0]), "r"(b[1]));
}

// ============ merged pre-pass: f32 -> f16 (rna), Q x0.125, V/P transposed ============
__global__ void prep_all(const float* __restrict__ Q, const float* __restrict__ K,
                         const float* __restrict__ V, const float* __restrict__ P) {
    const int x = blockIdx.x, bh = blockIdx.y, tid = threadIdx.x;
    if (x < 16) {
        size_t base = ((size_t)bh * MSEQ + x * 64) * DIMN;
        #pragma unroll
        for (int p = 0; p < 4; p++) {
            int idx = p * 256 + tid;
            float4 v = *(const float4*)(Q + base + (size_t)idx * 4);
            __half2 h0 = __floats2half2_rn(v.x * 0.125f, v.y * 0.125f);
            __half2 h1 = __floats2half2_rn(v.z * 0.125f, v.w * 0.125f);
            *(uint2*)(&g_Qh[base + (size_t)idx * 4]) =
                make_uint2(*(uint32_t*)&h0, *(uint32_t*)&h1);
        }
    } else if (x < 48) {
        size_t base = ((size_t)bh * KVROWS + (x - 16) * 64) * DIMN;
        #pragma unroll
        for (int p = 0; p < 4; p++) {
            int idx = p * 256 + tid;
            float4 v = *(const float4*)(K + base + (size_t)idx * 4);
            __half2 h0 = __floats2half2_rn(v.x, v.y);
            __half2 h1 = __floats2half2_rn(v.z, v.w);
            *(uint2*)(&g_Kh[base + (size_t)idx * 4]) =
                make_uint2(*(uint32_t*)&h0, *(uint32_t*)&h1);
        }
    } else if (x < 80) {
        __shared__ float ts[64][65];   // [j][d]
        const int j0 = (x - 48) * 64;
        size_t base = ((size_t)bh * KVROWS + j0) * DIMN;
        #pragma unroll
        for (int p = 0; p < 16; p++) {
            int idx = p * 256 + tid;
            ts[idx >> 6][idx & 63] = V[base + idx];
        }
        __syncthreads();
        const int d = tid >> 2, jq = (tid & 3) * 16;
        uint32_t u[8];
        #pragma unroll
        for (int q = 0; q < 8; q++) {
            __half2 h = __floats2half2_rn(ts[jq + 2 * q][d], ts[jq + 2 * q + 1][d]);
            u[q] = *(uint32_t*)&h;
        }
        __half* dst = &g_VTh[((size_t)bh * DIMN + d) * KVROWS + j0 + jq];
        *(uint4*)dst       = make_uint4(u[0], u[1], u[2], u[3]);
        *(uint4*)(dst + 8) = make_uint4(u[4], u[5], u[6], u[7]);
    } else {
        if (bh != 0) return;
        __shared__ float ts[64][65];   // [l][d]
        const int l0 = (x - 80) * 64;
        #pragma unroll
        for (int p = 0; p < 16; p++) {
            int idx = p * 256 + tid;
            int d = idx >> 6, lq = idx & 63;
            ts[lq][d] = P[(size_t)d * LSPAN + l0 + lq];
        }
        __syncthreads();
        const int lq = tid >> 2, dq = (tid & 3) * 16;
        uint32_t u[8];
        #pragma unroll
        for (int q = 0; q < 8; q++) {
            __half2 h = __floats2half2_rn(ts[lq][dq + 2 * q], ts[lq][dq + 2 * q + 1]);
            u[q] = *(uint32_t*)&h;
        }
        __half* dst = &g_PTh[(size_t)(l0 + lq) * DIMN + dq];
        *(uint4*)dst       = make_uint4(u[0], u[1], u[2], u[3]);
        *(uint4*)(dst + 8) = make_uint4(u[4], u[5], u[6], u[7]);
    }
}

// ============ main kernel: 1-tile software pipeline (PV lags S by one) ============
__global__ void __launch_bounds__(NTHR, 1) seqattn_f16_kernel(float* __restrict__ O) {
    extern __shared__ char sm[];
    const uint32_t sb = smem_u32(sm);

    float* psf = (float*)(sm + PS_B);
    float* Rs  = (float*)(sm + RS_B);

    const int tid  = threadIdx.x;
    const int w    = tid >> 5;
    const int lane = tid & 31;
    const int g    = lane >> 2;
    const int tig  = lane & 3;

    // 16 warps = 4 m-groups x 4 n-warps
    const int wm = w >> 2;
    const int wn = w & 3;
    // content window: 18 blocks of 8 cols; wn gets {5,5,4,4}
    const int nstart = (wn < 2) ? wn * 5 : 10 + (wn - 2) * 4;
    const int ncnt   = (wn < 2) ? 5 : 4;
    const int barid  = wm + 1;

    // LDSM lane addressing helpers
    const int lr = lane & 15;
    const int lk = lane >> 4;
    const int q4 = lane >> 3;
    const int rr = lane & 7;

    const int bh = blockIdx.y;
    const int m0 = blockIdx.x * BM;

    const __half* Qh  = g_Qh  + ((size_t)bh * MSEQ + m0) * DIMN;
    const __half* Kh  = g_Kh  + (size_t)bh * KVROWS * DIMN;
    const __half* VTh = g_VTh + (size_t)bh * DIMN * KVROWS;

    // ---- prologue: group c0 = {Q, K(0), PT(0)}; group c1 = {V(0)} ----
    {
        int r = tid >> 3, c = tid & 7;
        cp16(sb + QS_B + (uint32_t)(r * 72 + c * 8) * 2u, Qh + (size_t)r * DIMN + c * 8);
        #pragma unroll
        for (int p = 0; p < 3; p++) {
            int idx = p * NTHR + tid;
            int kr = idx >> 3, kc = idx & 7;
            cp16(sb + KS_B + (uint32_t)(kr * 72 + kc * 8) * 2u,
                 Kh + (size_t)(m0 + kr) * DIMN + kc * 8);
        }
        #pragma unroll
        for (int p = 0; p < 2; p++) {
            int idx = p * NTHR + tid;
            int pr = idx >> 3, pc = idx & 7;
            cp16(sb + PT_B + (uint32_t)(pr * 72 + pc * 8) * 2u,
                 g_PTh + (size_t)pr * DIMN + pc * 8);
        }
        CP_COMMIT();   // c0
        #pragma unroll
        for (int p = 0; p < 3; p++) {
            int idx = p * NTHR + tid;
            int d = idx / 24, c24 = idx % 24;
            cp16(sb + VT_B + (uint32_t)(d * 200 + c24 * 8) * 2u,
                 VTh + (size_t)d * KVROWS + m0 + c24 * 8);
        }
        CP_COMMIT();   // c1
    }
    if (tid < 64) Rs[tid] = 0.f;

    // lane-constant fragment base addresses
    const uint32_t aQbase = sb + QS_B + (uint32_t)((wm * 16 + lr) * QROWB + lk * 16);
    const uint32_t aWbase = sb + WS_B + (uint32_t)((wm * 16 + lr) * WROWB + lk * 16);
    const uint32_t sWbase = sb + WS_B + (uint32_t)((wm * 16 + lr) * WROWB);
    const uint32_t bRow  = (uint32_t)(((q4 >> 1) * 8 + rr) * QROWB + (q4 & 1) * 16);
    const uint32_t vRow  = (uint32_t)(((q4 >> 1) * 8 + rr) * WROWB + (q4 & 1) * 16);
    const uint32_t bRow2 = (uint32_t)(rr * QROWB + ((lane >> 3) & 1) * 16);

    CP_WAIT1();        // c0 done (Q,K0,PT0); c1 (V0) may pend
    __syncthreads();

    // ---- hoist Q fragments (tile-invariant) ----
    uint32_t aq[4][4];
    #pragma unroll
    for (int ks = 0; ks < 4; ks++) ldsm4(aq[ks], aQbase + ks * 32);

    float cO[2][4];
    #pragma unroll
    for (int b = 0; b < 2; b++)
        #pragma unroll
        for (int c = 0; c < 4; c++) cO[b][c] = 0.f;
    float rsv[2] = {0.f, 0.f};

    // ===== pipelined loop: iter t does S(t), exp(t), PV(t-1) =====
    for (int t = 0; t <= NT; t++) {
        const uint32_t ksOff = sb + KS_B + (uint32_t)(t & 1) * KSZB;
        const uint32_t ptOff = sb + PT_B + (uint32_t)(t & 1) * PSZB;
        const uint32_t vtOff = sb + VT_B + (uint32_t)((t - 1) & 1) * VSZB;

        CP_WAIT1();        // ensure K(t),PT(t) and V(t-1) resident (only V(t) may pend)
        __syncthreads();

        // issue K(t+1),PT(t+1) -> kbuf (t+1)&1 (K(t-1) retired)
        if (t + 1 < NT) {
            const int jg0n = m0 + (t + 1) * BL;
            const uint32_t kdst = sb + KS_B + (uint32_t)((t + 1) & 1) * KSZB;
            const uint32_t pdst = sb + PT_B + (uint32_t)((t + 1) & 1) * PSZB;
            #pragma unroll
            for (int p = 0; p < 3; p++) {
                int idx = p * NTHR + tid;
                int kr = idx >> 3, kc = idx & 7;
                cp16(kdst + (uint32_t)(kr * 72 + kc * 8) * 2u,
                     Kh + (size_t)(jg0n + kr) * DIMN + kc * 8);
            }
            #pragma unroll
            for (int p = 0; p < 2; p++) {
                int idx = p * NTHR + tid;
                int pr = idx >> 3, pc = idx & 7;
                cp16(pdst + (uint32_t)(pr * 72 + pc * 8) * 2u,
                     g_PTh + (size_t)((t + 1) * BL + pr) * DIMN + pc * 8);
            }
        }
        CP_COMMIT();

        float cC[5][4], cP[4][4];
        uint32_t hw2s[5][2];

        if (t < NT) {
            // ===== S GEMM: content (144-window) + pos, f32 acc =====
            #pragma unroll
            for (int nb = 0; nb < 5; nb++)
                #pragma unroll
                for (int c = 0; c < 4; c++) cC[nb][c] = 0.f;
            #pragma unroll
            for (int nb = 0; nb < 4; nb++)
                #pragma unroll
                for (int c = 0; c < 4; c++) cP[nb][c] = 0.f;

            #pragma unroll
            for (int ks = 0; ks < 4; ks++) {
                #pragma unroll
                for (int pp = 0; pp < 2; pp++) {      // pos: 2 x4 = 4 blocks
                    uint32_t bb[4];
                    ldsm4(bb, ptOff + (uint32_t)((wn * 32 + pp * 16) * QROWB) + bRow + ks * 32);
                    mma_f16_f32(cP[pp * 2],     aq[ks], bb);
                    mma_f16_f32(cP[pp * 2 + 1], aq[ks], bb + 2);
                }
                #pragma unroll
                for (int pp = 0; pp < 2; pp++) {      // content: 2 x4 = 4 blocks
                    uint32_t bb[4];
                    ldsm4(bb, ksOff + (uint32_t)((wm * 16 + (nstart + pp * 2) * 8) * QROWB) + bRow + ks * 32);
                    mma_f16_f32(cC[pp * 2],     aq[ks], bb);
                    mma_f16_f32(cC[pp * 2 + 1], aq[ks], bb + 2);
                }
                if (wn < 2) {                          // 5th content block (x2)
                    uint32_t b2[2];
                    ldsm2(b2, ksOff + (uint32_t)((wm * 16 + (nstart + 4) * 8) * QROWB) + bRow2 + ks * 32);
                    mma_f16_f32(cC[4], aq[ks], b2);
                }
            }

            // ---- pos scores x log2e -> posS ----
            #pragma unroll
            for (int nb = 0; nb < 4; nb++) {
                int lp = wn * 32 + nb * 8 + 2 * tig;
                int i1 = wm * 16 + g;
                *(float2*)(psf + i1 * PSF + lp) =
                    make_float2(cP[nb][0] * LOG2E_F, cP[nb][1] * LOG2E_F);
                *(float2*)(psf + (i1 + 8) * PSF + lp) =
                    make_float2(cP[nb][2] * LOG2E_F, cP[nb][3] * LOG2E_F);
            }
        }
        BAR_GRP(barid);   // posS(t) visible within m-group

        if (t < NT) {
            // ---- exp(t) into registers (no STSM yet) ----
            #pragma unroll
            for (int nb = 0; nb < 5; nb++) {
                if (nb < ncnt) {
                    int colrel = (nstart + nb) * 8 + 2 * tig;
                    #pragma unroll
                    for (int h = 0; h < 2; h++) {
                        int ig = g + 8 * h;
                        int i  = wm * 16 + ig;
                        float s0 = cC[nb][2 * h], s1 = cC[nb][2 * h + 1];
                        int l0 = colrel - ig;
                        float w0 = 0.f, w1 = 0.f;
                        if (l0 >= 0 && l0 < 128)
                            w0 = exp2f(fmaf(s0, LOG2E_F, psf[i * PSF + l0]));
                        if (l0 + 1 >= 0 && l0 + 1 < 128)
                            w1 = exp2f(fmaf(s1, LOG2E_F, psf[i * PSF + l0 + 1]));
                        __half2 hw = __floats2half2_rn(w0, w1);
                        float2 bk = __half22float2(hw);
                        rsv[h] += bk.x + bk.y;
                        hw2s[nb][h] = *(uint32_t*)&hw;
                    }
                }
            }
        }

        if (t > 0) {
            // ===== PV(t-1): per-warp 144-k window, W(t-1) + V(t-1) =====
            #pragma unroll
            for (int kk = 0; kk < 9; kk++) {
                uint32_t a[4];
                ldsm4(a, aWbase + kk * 32);
                uint32_t bv[4];
                ldsm4(bv, vtOff + (uint32_t)(wn * 16 * WROWB) + vRow + (uint32_t)(wm * 32 + kk * 32));
                mma_f16_f32(cO[0], a, bv);
                mma_f16_f32(cO[1], a, bv + 2);
            }
        }
        BAR_GRP(barid);   // group done reading W(t-1)

        if (t < NT) {
            // ---- STSM W(t) (group-private rows) ----
            #pragma unroll
            for (int nb = 0; nb < 5; nb++) {
                if (nb < ncnt)
                    stsm2(sWbase + (uint32_t)((nstart + nb) * 16), hw2s[nb][0], hw2s[nb][1]);
            }
        }
        __syncthreads();   // all groups done with V(t-1); W(t) visible for next iter

        // issue V(t+1) -> vbuf (t+1)&1 (V(t-1) retired)
        if (t + 1 < NT) {
            const int jg0n = m0 + (t + 1) * BL;
            const uint32_t vdst = sb + VT_B + (uint32_t)((t + 1) & 1) * VSZB;
            #pragma unroll
            for (int p = 0; p < 3; p++) {
                int idx = p * NTHR + tid;
                int d = idx / 24, c24 = idx % 24;
                cp16(vdst + (uint32_t)(d * 200 + c24 * 8) * 2u,
                     VTh + (size_t)d * KVROWS + jg0n + c24 * 8);
            }
        }
        CP_COMMIT();
    }

    // ---- rowsum reduction (cross-wn) ----
    #pragma unroll
    for (int h = 0; h < 2; h++) {
        float v = rsv[h];
        v += __shfl_xor_sync(0xffffffffu, v, 1);
        v += __shfl_xor_sync(0xffffffffu, v, 2);
        if (tig == 0) {
            int i = wm * 16 + g + 8 * h;
            atomicAdd(&Rs[i], v);
        }
    }
    __syncthreads();

    // ---- normalize + store (warp owns rows wm*16.., cols wn*16..) ----
    {
        int i1 = wm * 16 + g;
        float inv0 = 1.f / Rs[i1];
        float inv1 = 1.f / Rs[i1 + 8];
        #pragma unroll
        for (int nb = 0; nb < 2; nb++) {
            int d = wn * 16 + nb * 8 + 2 * tig;
            float2 o0 = make_float2(cO[nb][0] * inv0, cO[nb][1] * inv0);
            float2 o1 = make_float2(cO[nb][2] * inv1, cO[nb][3] * inv1);
            *(float2*)(O + ((size_t)bh * MSEQ + m0 + i1) * DIMN + d)     = o0;
            *(float2*)(O + ((size_t)bh * MSEQ + m0 + i1 + 8) * DIMN + d) = o1;
        }
    }
}

extern "C" void kernel_launch(void* const* d_in, const int* in_sizes, int n_in,
                              void* d_out, int out_size) {
    const float* Q = (const float*)d_in[0];
    const float* K = (const float*)d_in[1];
    const float* V = (const float*)d_in[2];
    const float* P = (const float*)d_in[3];
    float* O = (float*)d_out;
    (void)n_in; (void)in_sizes; (void)out_size;

    // single merged pre-pass (2 launches/replay -> ncu -s 5 lands on main kernel)
    prep_all<<<dim3(96, BHN), 256>>>(Q, K, V, P);

    cudaFuncSetAttribute(seqattn_f16_kernel,
                         cudaFuncAttributeMaxDynamicSharedMemorySize, SMEM_BYTES);
    dim3 grid(MSEQ / BM, BHN);   // (16, 64)
    seqattn_f16_kernel<<<grid, NTHR, SMEM_BYTES>>>(O);
}

// round 16
// speedup vs baseline: 1.2191x; 1.0033x over previous
#include <cuda_runtime.h>
#include <cuda_fp16.h>
#include <cstdint>
#include <math.h>

// -------- problem shape --------
#define BHN    64
#define MSEQ   1024
#define DIMN   64
#define LSPAN  1024
#define KVROWS (MSEQ + LSPAN)
#define BM     64
#define BL     128
#define NT     (LSPAN / BL)
#define NTHR   512

// -------- fp16 preconverted operands (device scratch; allocation-free) --------
__device__ __half g_Qh [(size_t)BHN * MSEQ  * DIMN];   //  8 MB, [bh][i][d]  (pre-scaled x0.125)
__device__ __half g_Kh [(size_t)BHN * KVROWS * DIMN];  // 16 MB, [bh][j][d]
__device__ __half g_VTh[(size_t)BHN * DIMN * KVROWS];  // 16 MB, [bh][d][j]
__device__ __half g_PTh[(size_t)LSPAN * DIMN];         // 128 KB, [l][d]

// -------- smem byte offsets (double-buffered K/VT/PT, single W/posS) --------
#define QS_B 0                      // Q  [64][72h]        =  9216
#define KS_B 9216                   // K  2x [192][72h]    = 55296
#define VT_B 64512                  // V^T 2x [64][200h]   = 51200
#define PT_B 115712                 // P^T 2x [128][72h]   = 36864
#define WS_B 152576                 // W  [64][200h]       = 25600
#define PS_B 178176                 // posS [64][148] f32  = 37888  (group-relative skewed)
#define RS_B 216064                 // rowsums [64] f32    =   256
#define SMEM_BYTES 216320

// buffer sizes in bytes
#define KSZB 27648
#define VSZB 25600
#define PSZB 18432

// -------- strides --------
#define QROWB 144     // Q/K/PT row stride bytes (72 halves)
#define WROWB 400     // W/VT row stride bytes (200 halves)
#define PSW 148       // posS f32 stride (EVEN — float2 reads at even col offsets)

#define LOG2E_F 1.4426950408889634f

__device__ __forceinline__ uint32_t smem_u32(const void* p) {
    uint32_t a;
    asm("{ .reg .u64 t; cvta.to.shared.u64 t, %1; cvt.u32.u64 %0, t; }" : "=r"(a) : "l"(p));
    return a;
}
__device__ __forceinline__ void cp16(uint32_t dst, const void* src) {
    asm volatile("cp.async.ca.shared.global [%0], [%1], 16;" :: "r"(dst), "l"(src) : "memory");
}
#define CP_COMMIT() asm volatile("cp.async.commit_group;" ::: "memory")
#define CP_WAIT1()  asm volatile("cp.async.wait_group 1;" ::: "memory")
#define BAR_GRP(id) asm volatile("bar.sync %0, 128;" :: "r"(id) : "memory")

__device__ __forceinline__ void ldsm4(uint32_t r[4], uint32_t a) {
    asm volatile("ldmatrix.sync.aligned.m8n8.x4.shared.b16 {%0,%1,%2,%3}, [%4];"
        : "=r"(r[0]), "=r"(r[1]), "=r"(r[2]), "=r"(r[3]) : "r"(a));
}
__device__ __forceinline__ void ldsm2(uint32_t r[2], uint32_t a) {
    asm volatile("ldmatrix.sync.aligned.m8n8.x2.shared.b16 {%0,%1}, [%2];"
        : "=r"(r[0]), "=r"(r[1]) : "r"(a));
}
__device__ __forceinline__ void stsm2(uint32_t a, uint32_t r0, uint32_t r1) {
    asm volatile("stmatrix.sync.aligned.m8n8.x2.shared.b16 [%0], {%1,%2};"
        :: "r"(a), "r"(r0), "r"(r1) : "memory");
}
__device__ __forceinline__ void mma_f16_f32(float c[4], const uint32_t a[4], const uint32_t b[2]) {
    asm volatile(
        "mma.sync.aligned.m16n8k16.row.col.f32.f16.f16.f32 "
        "{%0,%1,%2,%3}, {%4,%5,%6,%7}, {%8,%9}, {%0,%1,%2,%3};"
        : "+f"(c[0]), "+f"(c[1]), "+f"(c[2]), "+f"(c[3])
        : "r"(a[0]), "r"(a[1]), "r"(a[2]), "r"(a[3]), "r"(b[0]), "r"(b[1]));
}

// ============ merged pre-pass: f32 -> f16 (rna), Q x0.125, V/P transposed ============
__global__ void prep_all(const float* __restrict__ Q, const float* __restrict__ K,
                         const float* __restrict__ V, const float* __restrict__ P) {
    const int x = blockIdx.x, bh = blockIdx.y, tid = threadIdx.x;
    if (x < 16) {
        size_t base = ((size_t)bh * MSEQ + x * 64) * DIMN;
        #pragma unroll
        for (int p = 0; p < 4; p++) {
            int idx = p * 256 + tid;
            float4 v = *(const float4*)(Q + base + (size_t)idx * 4);
            __half2 h0 = __floats2half2_rn(v.x * 0.125f, v.y * 0.125f);
            __half2 h1 = __floats2half2_rn(v.z * 0.125f, v.w * 0.125f);
            *(uint2*)(&g_Qh[base + (size_t)idx * 4]) =
                make_uint2(*(uint32_t*)&h0, *(uint32_t*)&h1);
        }
    } else if (x < 48) {
        size_t base = ((size_t)bh * KVROWS + (x - 16) * 64) * DIMN;
        #pragma unroll
        for (int p = 0; p < 4; p++) {
            int idx = p * 256 + tid;
            float4 v = *(const float4*)(K + base + (size_t)idx * 4);
            __half2 h0 = __floats2half2_rn(v.x, v.y);
            __half2 h1 = __floats2half2_rn(v.z, v.w);
            *(uint2*)(&g_Kh[base + (size_t)idx * 4]) =
                make_uint2(*(uint32_t*)&h0, *(uint32_t*)&h1);
        }
    } else if (x < 80) {
        __shared__ float ts[64][65];   // [j][d]
        const int j0 = (x - 48) * 64;
        size_t base = ((size_t)bh * KVROWS + j0) * DIMN;
        #pragma unroll
        for (int p = 0; p < 16; p++) {
            int idx = p * 256 + tid;
            ts[idx >> 6][idx & 63] = V[base + idx];
        }
        __syncthreads();
        const int d = tid >> 2, jq = (tid & 3) * 16;
        uint32_t u[8];
        #pragma unroll
        for (int q = 0; q < 8; q++) {
            __half2 h = __floats2half2_rn(ts[jq + 2 * q][d], ts[jq + 2 * q + 1][d]);
            u[q] = *(uint32_t*)&h;
        }
        __half* dst = &g_VTh[((size_t)bh * DIMN + d) * KVROWS + j0 + jq];
        *(uint4*)dst       = make_uint4(u[0], u[1], u[2], u[3]);
        *(uint4*)(dst + 8) = make_uint4(u[4], u[5], u[6], u[7]);
    } else {
        if (bh != 0) return;
        __shared__ float ts[64][65];   // [l][d]
        const int l0 = (x - 80) * 64;
        #pragma unroll
        for (int p = 0; p < 16; p++) {
            int idx = p * 256 + tid;
            int d = idx >> 6, lq = idx & 63;
            ts[lq][d] = P[(size_t)d * LSPAN + l0 + lq];
        }
        __syncthreads();
        const int lq = tid >> 2, dq = (tid & 3) * 16;
        uint32_t u[8];
        #pragma unroll
        for (int q = 0; q < 8; q++) {
            __half2 h = __floats2half2_rn(ts[lq][dq + 2 * q], ts[lq][dq + 2 * q + 1]);
            u[q] = *(uint32_t*)&h;
        }
        __half* dst = &g_PTh[(size_t)(l0 + lq) * DIMN + dq];
        *(uint4*)dst       = make_uint4(u[0], u[1], u[2], u[3]);
        *(uint4*)(dst + 8) = make_uint4(u[4], u[5], u[6], u[7]);
    }
}

// ============ main kernel: pipelined, skewed posS layout ============
__global__ void __launch_bounds__(NTHR, 1) seqattn_f16_kernel(float* __restrict__ O) {
    extern __shared__ char sm[];
    const uint32_t sb = smem_u32(sm);

    float* psf = (float*)(sm + PS_B);
    float* Rs  = (float*)(sm + RS_B);

    const int tid  = threadIdx.x;
    const int w    = tid >> 5;
    const int lane = tid & 31;
    const int g    = lane >> 2;
    const int tig  = lane & 3;

    // 16 warps = 4 m-groups x 4 n-warps
    const int wm = w >> 2;
    const int wn = w & 3;
    // content window: 18 blocks of 8 cols; wn gets {5,5,4,4}
    const int nstart = (wn < 2) ? wn * 5 : 10 + (wn - 2) * 4;
    const int ncnt   = (wn < 2) ? 5 : 4;
    const int barid  = wm + 1;

    // LDSM lane addressing helpers
    const int lr = lane & 15;
    const int lk = lane >> 4;
    const int q4 = lane >> 3;
    const int rr = lane & 7;

    const int bh = blockIdx.y;
    const int m0 = blockIdx.x * BM;

    const __half* Qh  = g_Qh  + ((size_t)bh * MSEQ + m0) * DIMN;
    const __half* Kh  = g_Kh  + (size_t)bh * KVROWS * DIMN;
    const __half* VTh = g_VTh + (size_t)bh * DIMN * KVROWS;

    // ---- prologue: group c0 = {Q, K(0), PT(0)}; group c1 = {V(0)} ----
    {
        int r = tid >> 3, c = tid & 7;
        cp16(sb + QS_B + (uint32_t)(r * 72 + c * 8) * 2u, Qh + (size_t)r * DIMN + c * 8);
        #pragma unroll
        for (int p = 0; p < 3; p++) {
            int idx = p * NTHR + tid;
            int kr = idx >> 3, kc = idx & 7;
            cp16(sb + KS_B + (uint32_t)(kr * 72 + kc * 8) * 2u,
                 Kh + (size_t)(m0 + kr) * DIMN + kc * 8);
        }
        #pragma unroll
        for (int p = 0; p < 2; p++) {
            int idx = p * NTHR + tid;
            int pr = idx >> 3, pc = idx & 7;
            cp16(sb + PT_B + (uint32_t)(pr * 72 + pc * 8) * 2u,
                 g_PTh + (size_t)pr * DIMN + pc * 8);
        }
        CP_COMMIT();   // c0
        #pragma unroll
        for (int p = 0; p < 3; p++) {
            int idx = p * NTHR + tid;
            int d = idx / 24, c24 = idx % 24;
            cp16(sb + VT_B + (uint32_t)(d * 200 + c24 * 8) * 2u,
                 VTh + (size_t)d * KVROWS + m0 + c24 * 8);
        }
        CP_COMMIT();   // c1
    }
    if (tid < 64) Rs[tid] = 0.f;

    // lane-constant fragment base addresses
    const uint32_t aQbase = sb + QS_B + (uint32_t)((wm * 16 + lr) * QROWB + lk * 16);
    const uint32_t aWbase = sb + WS_B + (uint32_t)((wm * 16 + lr) * WROWB + lk * 16);
    const uint32_t sWbase = sb + WS_B + (uint32_t)((wm * 16 + lr) * WROWB);
    const uint32_t bRow  = (uint32_t)(((q4 >> 1) * 8 + rr) * QROWB + (q4 & 1) * 16);
    const uint32_t vRow  = (uint32_t)(((q4 >> 1) * 8 + rr) * WROWB + (q4 & 1) * 16);
    const uint32_t bRow2 = (uint32_t)(rr * QROWB + ((lane >> 3) & 1) * 16);

    CP_WAIT1();        // c0 done (Q,K0,PT0); c1 (V0) may pend
    __syncthreads();

    // ---- hoist Q fragments (tile-invariant) ----
    uint32_t aq[4][4];
    #pragma unroll
    for (int ks = 0; ks < 4; ks++) ldsm4(aq[ks], aQbase + ks * 32);

    float cO[2][4];
    #pragma unroll
    for (int b = 0; b < 2; b++)
        #pragma unroll
        for (int c = 0; c < 4; c++) cO[b][c] = 0.f;
    float rsv[2] = {0.f, 0.f};

    // ===== pipelined loop: iter t does S(t), exp(t), PV(t-1) =====
    for (int t = 0; t <= NT; t++) {
        const uint32_t ksOff = sb + KS_B + (uint32_t)(t & 1) * KSZB;
        const uint32_t ptOff = sb + PT_B + (uint32_t)(t & 1) * PSZB;
        const uint32_t vtOff = sb + VT_B + (uint32_t)((t - 1) & 1) * VSZB;

        CP_WAIT1();        // K(t),PT(t),V(t-1) resident (only V(t) may pend)
        __syncthreads();

        // issue K(t+1),PT(t+1) -> kbuf (t+1)&1
        if (t + 1 < NT) {
            const int jg0n = m0 + (t + 1) * BL;
            const uint32_t kdst = sb + KS_B + (uint32_t)((t + 1) & 1) * KSZB;
            const uint32_t pdst = sb + PT_B + (uint32_t)((t + 1) & 1) * PSZB;
            #pragma unroll
            for (int p = 0; p < 3; p++) {
                int idx = p * NTHR + tid;
                int kr = idx >> 3, kc = idx & 7;
                cp16(kdst + (uint32_t)(kr * 72 + kc * 8) * 2u,
                     Kh + (size_t)(jg0n + kr) * DIMN + kc * 8);
            }
            #pragma unroll
            for (int p = 0; p < 2; p++) {
                int idx = p * NTHR + tid;
                int pr = idx >> 3, pc = idx & 7;
                cp16(pdst + (uint32_t)(pr * 72 + pc * 8) * 2u,
                     g_PTh + (size_t)((t + 1) * BL + pr) * DIMN + pc * 8);
            }
        }
        CP_COMMIT();

        float cC[5][4], cP[4][4];
        uint32_t hw2s[5][2];

        if (t < NT) {
            // ===== S GEMM: content (144-window) + pos, f32 acc =====
            #pragma unroll
            for (int nb = 0; nb < 5; nb++)
                #pragma unroll
                for (int c = 0; c < 4; c++) cC[nb][c] = 0.f;
            #pragma unroll
            for (int nb = 0; nb < 4; nb++)
                #pragma unroll
                for (int c = 0; c < 4; c++) cP[nb][c] = 0.f;

            #pragma unroll
            for (int ks = 0; ks < 4; ks++) {
                #pragma unroll
                for (int pp = 0; pp < 2; pp++) {      // pos: 2 x4 = 4 blocks
                    uint32_t bb[4];
                    ldsm4(bb, ptOff + (uint32_t)((wn * 32 + pp * 16) * QROWB) + bRow + ks * 32);
                    mma_f16_f32(cP[pp * 2],     aq[ks], bb);
                    mma_f16_f32(cP[pp * 2 + 1], aq[ks], bb + 2);
                }
                #pragma unroll
                for (int pp = 0; pp < 2; pp++) {      // content: 2 x4 = 4 blocks
                    uint32_t bb[4];
                    ldsm4(bb, ksOff + (uint32_t)((wm * 16 + (nstart + pp * 2) * 8) * QROWB) + bRow + ks * 32);
                    mma_f16_f32(cC[pp * 2],     aq[ks], bb);
                    mma_f16_f32(cC[pp * 2 + 1], aq[ks], bb + 2);
                }
                if (wn < 2) {                          // 5th content block (x2)
                    uint32_t b2[2];
                    ldsm2(b2, ksOff + (uint32_t)((wm * 16 + (nstart + 4) * 8) * QROWB) + bRow2 + ks * 32);
                    mma_f16_f32(cC[4], aq[ks], b2);
                }
            }

            // ---- pos scores x log2e -> posS, SKEWED group-relative cols ----
            // slot(i, l) = psf[i*PSW + (ig + l)], ig = i - wm*16; reader col is even.
            #pragma unroll
            for (int nb = 0; nb < 4; nb++) {
                int lp = wn * 32 + nb * 8 + 2 * tig;
                int i1 = wm * 16 + g;          // ig = g
                int i2 = i1 + 8;               // ig = g + 8
                psf[i1 * PSW + (g + lp)]          = cP[nb][0] * LOG2E_F;
                psf[i1 * PSW + (g + lp + 1)]      = cP[nb][1] * LOG2E_F;
                psf[i2 * PSW + (g + 8 + lp)]      = cP[nb][2] * LOG2E_F;
                psf[i2 * PSW + (g + 8 + lp + 1)]  = cP[nb][3] * LOG2E_F;
            }
        }
        BAR_GRP(barid);   // posS(t) visible within m-group

        if (t < NT) {
            // ---- exp(t) into registers; posS reads are aligned float2 ----
            #pragma unroll
            for (int nb = 0; nb < 5; nb++) {
                if (nb < ncnt) {
                    int colrel = (nstart + nb) * 8 + 2 * tig;   // even
                    #pragma unroll
                    for (int h = 0; h < 2; h++) {
                        int ig = g + 8 * h;
                        int i  = wm * 16 + ig;
                        float2 pv = *(const float2*)(psf + i * PSW + colrel);
                        float s0 = cC[nb][2 * h], s1 = cC[nb][2 * h + 1];
                        int l0 = colrel - ig;
                        float w0 = 0.f, w1 = 0.f;
                        if (l0 >= 0 && l0 < 128)
                            w0 = exp2f(fmaf(s0, LOG2E_F, pv.x));
                        if (l0 + 1 >= 0 && l0 + 1 < 128)
                            w1 = exp2f(fmaf(s1, LOG2E_F, pv.y));
                        __half2 hw = __floats2half2_rn(w0, w1);
                        float2 bk = __half22float2(hw);
                        rsv[h] += bk.x + bk.y;
                        hw2s[nb][h] = *(uint32_t*)&hw;
                    }
                }
            }
        }

        if (t > 0) {
            // ===== PV(t-1): per-warp 144-k window, W(t-1) + V(t-1) =====
            #pragma unroll
            for (int kk = 0; kk < 9; kk++) {
                uint32_t a[4];
                ldsm4(a, aWbase + kk * 32);
                uint32_t bv[4];
                ldsm4(bv, vtOff + (uint32_t)(wn * 16 * WROWB) + vRow + (uint32_t)(wm * 32 + kk * 32));
                mma_f16_f32(cO[0], a, bv);
                mma_f16_f32(cO[1], a, bv + 2);
            }
        }
        BAR_GRP(barid);   // group done reading W(t-1)

        if (t < NT) {
            // ---- STSM W(t) (group-private rows) ----
            #pragma unroll
            for (int nb = 0; nb < 5; nb++) {
                if (nb < ncnt)
                    stsm2(sWbase + (uint32_t)((nstart + nb) * 16), hw2s[nb][0], hw2s[nb][1]);
            }
        }
        __syncthreads();   // all groups done with V(t-1); W(t) visible next iter

        // issue V(t+1) -> vbuf (t+1)&1
        if (t + 1 < NT) {
            const int jg0n = m0 + (t + 1) * BL;
            const uint32_t vdst = sb + VT_B + (uint32_t)((t + 1) & 1) * VSZB;
            #pragma unroll
            for (int p = 0; p < 3; p++) {
                int idx = p * NTHR + tid;
                int d = idx / 24, c24 = idx % 24;
                cp16(vdst + (uint32_t)(d * 200 + c24 * 8) * 2u,
                     VTh + (size_t)d * KVROWS + jg0n + c24 * 8);
            }
        }
        CP_COMMIT();
    }

    // ---- rowsum reduction (cross-wn) ----
    #pragma unroll
    for (int h = 0; h < 2; h++) {
        float v = rsv[h];
        v += __shfl_xor_sync(0xffffffffu, v, 1);
        v += __shfl_xor_sync(0xffffffffu, v, 2);
        if (tig == 0) {
            int i = wm * 16 + g + 8 * h;
            atomicAdd(&Rs[i], v);
        }
    }
    __syncthreads();

    // ---- normalize + store (warp owns rows wm*16.., cols wn*16..) ----
    {
        int i1 = wm * 16 + g;
        float inv0 = 1.f / Rs[i1];
        float inv1 = 1.f / Rs[i1 + 8];
        #pragma unroll
        for (int nb = 0; nb < 2; nb++) {
            int d = wn * 16 + nb * 8 + 2 * tig;
            float2 o0 = make_float2(cO[nb][0] * inv0, cO[nb][1] * inv0);
            float2 o1 = make_float2(cO[nb][2] * inv1, cO[nb][3] * inv1);
            *(float2*)(O + ((size_t)bh * MSEQ + m0 + i1) * DIMN + d)     = o0;
            *(float2*)(O + ((size_t)bh * MSEQ + m0 + i1 + 8) * DIMN + d) = o1;
        }
    }
}

extern "C" void kernel_launch(void* const* d_in, const int* in_sizes, int n_in,
                              void* d_out, int out_size) {
    const float* Q = (const float*)d_in[0];
    const float* K = (const float*)d_in[1];
    const float* V = (const float*)d_in[2];
    const float* P = (const float*)d_in[3];
    float* O = (float*)d_out;
    (void)n_in; (void)in_sizes; (void)out_size;

    prep_all<<<dim3(96, BHN), 256>>>(Q, K, V, P);

    cudaFuncSetAttribute(seqattn_f16_kernel,
                         cudaFuncAttributeMaxDynamicSharedMemorySize, SMEM_BYTES);
    dim3 grid(MSEQ / BM, BHN);   // (16, 64)
    seqattn_f16_kernel<<<grid, NTHR, SMEM_BYTES>>>(O);
}